// round 12
// baseline (speedup 1.0000x reference)
#include <cuda_runtime.h>
#include <cuda_bf16.h>
#include <math.h>

#define L 768
#define D 256
#define H 8
#define DK 32
#define DFF 1024
#define NB 64
#define NLAYER 8

// ---------------- device scratch ----------------
__device__ float g_x[L * D];
__device__ float g_h[L * D];
__device__ float g_q[L * D];
__device__ float g_k[L * D];
__device__ float g_v[L * D];
__device__ float g_attn[L * D];
__device__ float g_ff[L * DFF];
__device__ float g_pq[L * D];
__device__ float g_pk[L * D];
__device__ float g_E1[NB * D];
__device__ unsigned g_W1t[D * D];
__device__ int   g_bucket[L * L];
__device__ float g_relbias[H * 1536];
__device__ float g_dummy[L * DFF];

// pre-split transposed weights (bf16 hi/lo, [layer][n][k])
__device__ __nv_bfloat16 g_wq_hi[NLAYER * D * D], g_wq_lo[NLAYER * D * D];
__device__ __nv_bfloat16 g_wk_hi[NLAYER * D * D], g_wk_lo[NLAYER * D * D];
__device__ __nv_bfloat16 g_wv_hi[NLAYER * D * D], g_wv_lo[NLAYER * D * D];
__device__ __nv_bfloat16 g_wo_hi[NLAYER * D * D], g_wo_lo[NLAYER * D * D];
__device__ __nv_bfloat16 g_f1_hi[NLAYER * D * DFF], g_f1_lo[NLAYER * D * DFF];
__device__ __nv_bfloat16 g_f2_hi[NLAYER * DFF * D], g_f2_lo[NLAYER * DFF * D];
__device__ __nv_bfloat16 g_pqw_hi[D * D], g_pqw_lo[D * D];
__device__ __nv_bfloat16 g_pkw_hi[D * D], g_pkw_lo[D * D];

// ---------------- bucket table (pair head epilogue needs it) ----------------
__global__ void bucket_kernel(int* __restrict__ bucket) {
    int idx = blockIdx.x * blockDim.x + threadIdx.x;
    if (idx >= L * L) return;
    int i = idx / L, j = idx % L;
    int rel = i - j;
    int ret = (rel < 0) ? 32 : 0;
    int arp = abs(rel);
    int val;
    if (arp < 16) {
        val = arp;
    } else {
        float safe = (float)(arp < 1 ? 1 : arp);
        float t = logf(safe / 16.0f) / 2.7725887f * 16.0f;
        int vil = 16 + (int)t;
        val = vil < 31 ? vil : 31;
    }
    bucket[idx] = ret + val;
}

// relbias[h][rel + 768] = rp_emb[bucket(rel) * H + h]
__global__ void relbias_kernel(const float* __restrict__ rp_emb,
                               float* __restrict__ relbias) {
    int idx = blockIdx.x * 256 + threadIdx.x;
    if (idx >= H * 1536) return;
    int h = idx / 1536, r = idx % 1536;
    int rel = r - 768;
    int ret = (rel < 0) ? 32 : 0;
    int arp = abs(rel);
    int val;
    if (arp < 16) {
        val = arp;
    } else {
        float safe = (float)(arp < 1 ? 1 : arp);
        float t = logf(safe / 16.0f) / 2.7725887f * 16.0f;
        int vil = 16 + (int)t;
        val = vil < 31 ? vil : 31;
    }
    relbias[idx] = rp_emb[(ret + val) * H + h];
}

// ---------------- embedding ----------------
__global__ void embed_kernel(const int* __restrict__ seq,
                             const float* __restrict__ tok_emb,
                             float* __restrict__ x) {
    int l = blockIdx.x;
    int d = threadIdx.x;
    x[l * D + d] = tok_emb[seq[l] * D + d];
}

// ---------------- layernorm ----------------
__global__ void ln_kernel(const float* __restrict__ x,
                          const float* __restrict__ s,
                          const float* __restrict__ b,
                          float* __restrict__ out) {
    int row = blockIdx.x;
    int tid = threadIdx.x;
    float val = x[row * D + tid];
    float s1 = val, s2 = val * val;
#pragma unroll
    for (int o = 16; o > 0; o >>= 1) {
        s1 += __shfl_xor_sync(0xffffffffu, s1, o);
        s2 += __shfl_xor_sync(0xffffffffu, s2, o);
    }
    __shared__ float r1[8], r2[8];
    if ((tid & 31) == 0) { r1[tid >> 5] = s1; r2[tid >> 5] = s2; }
    __syncthreads();
    float t1 = 0.f, t2 = 0.f;
#pragma unroll
    for (int w = 0; w < 8; w++) { t1 += r1[w]; t2 += r2[w]; }
    float m = t1 * (1.0f / D);
    float var = t2 * (1.0f / D) - m * m;
    out[row * D + tid] = (val - m) * rsqrtf(var + 1e-5f) * s[tid] + b[tid];
}

// ---------------- weight pre-split ----------------
__global__ void presplit_kernel(const float* __restrict__ W,
                                __nv_bfloat16* __restrict__ hiT,
                                __nv_bfloat16* __restrict__ loT,
                                int K, int N, int total) {
    int idx = blockIdx.x * 256 + threadIdx.x;
    if (idx >= total) return;
    int kn = K * N;
    int l = idx / kn;
    int r = idx - l * kn;
    int k = r / N, n = r - k * N;
    float a = W[idx];
    __nv_bfloat16 h = __float2bfloat16(a);
    size_t o = ((size_t)l * N + n) * K + k;
    hiT[o] = h;
    loT[o] = __float2bfloat16(a - __bfloat162float(h));
}

// ---------------- bf16-split HMMA GEMM (R10 256-thread config) -------------
__device__ __forceinline__ float gelu_exact(float x) {
    return 0.5f * x * (1.0f + erff(x * 0.70710678118654752f));
}

__device__ __forceinline__ void mma_bf16(float* c, const unsigned* a, unsigned b0, unsigned b1) {
    asm volatile(
        "mma.sync.aligned.m16n8k16.row.col.f32.bf16.bf16.f32 "
        "{%0,%1,%2,%3}, {%4,%5,%6,%7}, {%8,%9}, {%0,%1,%2,%3};"
        : "+f"(c[0]), "+f"(c[1]), "+f"(c[2]), "+f"(c[3])
        : "r"(a[0]), "r"(a[1]), "r"(a[2]), "r"(a[3]), "r"(b0), "r"(b1));
}

__device__ __forceinline__ unsigned packsplit(float a, float b, unsigned& lo) {
    __nv_bfloat16 ha = __float2bfloat16(a), hb = __float2bfloat16(b);
    __nv_bfloat16 la = __float2bfloat16(a - __bfloat162float(ha));
    __nv_bfloat16 lb = __float2bfloat16(b - __bfloat162float(hb));
    lo = (unsigned)__bfloat16_as_ushort(la) | ((unsigned)__bfloat16_as_ushort(lb) << 16);
    return (unsigned)__bfloat16_as_ushort(ha) | ((unsigned)__bfloat16_as_ushort(hb) << 16);
}

#define HPAD 20

template <int EPI>
__device__ __forceinline__ void hgemm_body(
    const float* __restrict__ A, const __nv_bfloat16* __restrict__ BhiT,
    const __nv_bfloat16* __restrict__ BloT, float* __restrict__ C,
    const float* __restrict__ bias, const float* __restrict__ res,
    int M, int N, int K, int bx, int by)
{
    __shared__ unsigned sAhi[64 * HPAD], sAlo[64 * HPAD];
    __shared__ unsigned sBhi[64 * HPAD], sBlo[64 * HPAD];
    const int tid = threadIdx.x;
    const int lane = tid & 31, warp = tid >> 5;
    const int gid = lane >> 2, tig = lane & 3;
    const int wm = warp >> 2, wn = warp & 3;
    const int row0 = by * 64, col0 = bx * 64;

    float acc[2][2][4] = {};

    const int arow = tid >> 3;
    const int akq  = (tid & 7) * 4;
    const int bn   = tid >> 2;
    const int bq   = (tid & 3) * 4;

    for (int k0 = 0; k0 < K; k0 += 32) {
        __syncthreads();
#pragma unroll
        for (int t = 0; t < 2; t++) {
            int row = arow + t * 32;
            float4 av = *(const float4*)(A + (size_t)(row0 + row) * K + k0 + akq);
            unsigned lo01, lo23;
            unsigned hi01 = packsplit(av.x, av.y, lo01);
            unsigned hi23 = packsplit(av.z, av.w, lo23);
            uint2 hv; hv.x = hi01; hv.y = hi23;
            uint2 lv; lv.x = lo01; lv.y = lo23;
            *(uint2*)&sAhi[row * HPAD + (akq >> 1)] = hv;
            *(uint2*)&sAlo[row * HPAD + (akq >> 1)] = lv;
        }
        {
            const size_t go = (size_t)(col0 + bn) * K + k0 + bq * 2;
            *(uint4*)&sBhi[bn * HPAD + bq] = *(const uint4*)(BhiT + go);
            *(uint4*)&sBlo[bn * HPAD + bq] = *(const uint4*)(BloT + go);
        }
        __syncthreads();
#pragma unroll
        for (int ks = 0; ks < 2; ks++) {
            const int kb = ks * 8;
            unsigned ahi[2][4], alo[2][4];
#pragma unroll
            for (int mi = 0; mi < 2; mi++) {
                int R = wm * 32 + mi * 16;
                ahi[mi][0] = sAhi[(R + gid) * HPAD + kb + tig];
                ahi[mi][1] = sAhi[(R + gid + 8) * HPAD + kb + tig];
                ahi[mi][2] = sAhi[(R + gid) * HPAD + kb + tig + 4];
                ahi[mi][3] = sAhi[(R + gid + 8) * HPAD + kb + tig + 4];
                alo[mi][0] = sAlo[(R + gid) * HPAD + kb + tig];
                alo[mi][1] = sAlo[(R + gid + 8) * HPAD + kb + tig];
                alo[mi][2] = sAlo[(R + gid) * HPAD + kb + tig + 4];
                alo[mi][3] = sAlo[(R + gid + 8) * HPAD + kb + tig + 4];
            }
#pragma unroll
            for (int ni = 0; ni < 2; ni++) {
                int nc = wn * 16 + ni * 8;
                unsigned bh0 = sBhi[(nc + gid) * HPAD + kb + tig];
                unsigned bh1 = sBhi[(nc + gid) * HPAD + kb + tig + 4];
                unsigned bl0 = sBlo[(nc + gid) * HPAD + kb + tig];
                unsigned bl1 = sBlo[(nc + gid) * HPAD + kb + tig + 4];
#pragma unroll
                for (int mi = 0; mi < 2; mi++) {
                    mma_bf16(acc[mi][ni], ahi[mi], bh0, bh1);
                    mma_bf16(acc[mi][ni], ahi[mi], bl0, bl1);
                    mma_bf16(acc[mi][ni], alo[mi], bh0, bh1);
                }
            }
        }
    }

#pragma unroll
    for (int mi = 0; mi < 2; mi++) {
#pragma unroll
        for (int ni = 0; ni < 2; ni++) {
            int m0 = row0 + wm * 32 + mi * 16 + gid;
            int n = col0 + wn * 16 + ni * 8 + tig * 2;
            float v0 = acc[mi][ni][0], v1 = acc[mi][ni][1];
            float v2 = acc[mi][ni][2], v3 = acc[mi][ni][3];
            if (EPI == 1 || EPI == 2 || EPI == 3) {
                float2 bb = *(const float2*)&bias[n];
                v0 += bb.x; v1 += bb.y; v2 += bb.x; v3 += bb.y;
            }
            if (EPI == 2) {
                v0 = gelu_exact(v0); v1 = gelu_exact(v1);
                v2 = gelu_exact(v2); v3 = gelu_exact(v3);
            }
            if (EPI == 3 || EPI == 4) {
                float2 r0 = *(const float2*)&res[(size_t)m0 * N + n];
                float2 r1 = *(const float2*)&res[(size_t)(m0 + 8) * N + n];
                v0 += r0.x; v1 += r0.y; v2 += r1.x; v3 += r1.y;
            }
            float2 o0; o0.x = v0; o0.y = v1;
            float2 o1; o1.x = v2; o1.y = v3;
            *(float2*)&C[(size_t)m0 * N + n] = o0;
            *(float2*)&C[(size_t)(m0 + 8) * N + n] = o1;
        }
    }
}

template <int EPI>
__global__ void __launch_bounds__(256, 3)
hgemm_kernel(const float* __restrict__ A, const __nv_bfloat16* __restrict__ BhiT,
             const __nv_bfloat16* __restrict__ BloT, float* __restrict__ C,
             const float* __restrict__ bias, const float* __restrict__ res,
             int M, int N, int K) {
    hgemm_body<EPI>(A, BhiT, BloT, C, bias, res, M, N, K, blockIdx.x, blockIdx.y);
}

__global__ void __launch_bounds__(256, 3)
hgemm_qkv_kernel(const float* __restrict__ A, int layer,
                 float* __restrict__ q, float* __restrict__ k, float* __restrict__ v) {
    const size_t off = (size_t)layer * D * D;
    const __nv_bfloat16 *bh, *bl;
    float* C;
    if (blockIdx.z == 0)      { bh = g_wq_hi + off; bl = g_wq_lo + off; C = q; }
    else if (blockIdx.z == 1) { bh = g_wk_hi + off; bl = g_wk_lo + off; C = k; }
    else                      { bh = g_wv_hi + off; bl = g_wv_lo + off; C = v; }
    hgemm_body<0>(A, bh, bl, C, nullptr, nullptr, L, D, D, blockIdx.x, blockIdx.y);
}

__global__ void __launch_bounds__(256, 3)
hgemm_pqpk_kernel(const float* __restrict__ A,
                  const float* __restrict__ bq, const float* __restrict__ bk,
                  float* __restrict__ pq, float* __restrict__ pk) {
    const __nv_bfloat16 *bh, *bl;
    const float* bias;
    float* C;
    if (blockIdx.z == 0) { bh = g_pqw_hi; bl = g_pqw_lo; bias = bq; C = pq; }
    else                 { bh = g_pkw_hi; bl = g_pkw_lo; bias = bk; C = pk; }
    hgemm_body<1>(A, bh, bl, C, bias, nullptr, L, D, D, blockIdx.x, blockIdx.y);
}

// ---------------- attention v3: relbias slice in smem, low regs -------------
#define QT 16
// floats: sq 512 + sbias 784 + sp 12288 + sinv 16
#define ATTN_SMEM ((QT * DK + 784 + QT * L + QT) * 4)
__global__ void __launch_bounds__(256, 3)
attn3_kernel(const float* __restrict__ q, const float* __restrict__ k,
             const float* __restrict__ v, const float* __restrict__ relbias,
             float* __restrict__ out) {
    extern __shared__ unsigned char smraw[];
    float* sq = (float*)smraw;            // [16][32]
    float* sbias = sq + QT * DK;          // [784]
    float* sp = sbias + 784;              // [16][768]
    float* sinv = sp + QT * L;            // [16]
    const int i0 = blockIdx.x * QT;
    const int h = blockIdx.y;
    const int tid = threadIdx.x;
    const float invscale = 0.17677669529663687f;

    for (int t = tid; t < QT * DK; t += 256)
        sq[t] = q[(i0 + (t >> 5)) * D + h * DK + (t & 31)];
    // sbias[t] = relbias[h][i0 + 1 + t], t in [0, 783); access sbias[qi - j + 767]
    for (int t = tid; t < 783; t += 256)
        sbias[t] = relbias[h * 1536 + i0 + 1 + t];
    __syncthreads();

    // pass 1: scores (dot-register accumulation, broadcast LDS for q)
    for (int j = tid; j < L; j += 256) {
        float4 kv[8];
        const float4* kr = (const float4*)(k + (size_t)j * D + h * DK);
#pragma unroll
        for (int t = 0; t < 8; t++) kv[t] = kr[t];
        float dot[QT];
#pragma unroll
        for (int qi = 0; qi < QT; qi++) dot[qi] = 0.f;
#pragma unroll
        for (int t = 0; t < 8; t++) {
#pragma unroll
            for (int qi = 0; qi < QT; qi++) {
                float4 qv = *(const float4*)(sq + qi * DK + t * 4);
                dot[qi] += qv.x * kv[t].x + qv.y * kv[t].y + qv.z * kv[t].z + qv.w * kv[t].w;
            }
        }
#pragma unroll
        for (int qi = 0; qi < QT; qi++)
            sp[qi * L + j] = dot[qi] * invscale + sbias[qi - j + 767];
    }
    __syncthreads();

    // softmax: warp w handles qi = 2w, 2w+1
    const int warp = tid >> 5, lane = tid & 31;
#pragma unroll
    for (int qq = 0; qq < 2; qq++) {
        int qi = warp * 2 + qq;
        float m = -1e30f;
        for (int j = lane; j < L; j += 32) m = fmaxf(m, sp[qi * L + j]);
#pragma unroll
        for (int o = 16; o > 0; o >>= 1) m = fmaxf(m, __shfl_xor_sync(0xffffffffu, m, o));
        float s = 0.f;
        for (int j = lane; j < L; j += 32) {
            float e = expf(sp[qi * L + j] - m);
            sp[qi * L + j] = e;
            s += e;
        }
#pragma unroll
        for (int o = 16; o > 0; o >>= 1) s += __shfl_xor_sync(0xffffffffu, s, o);
        if (lane == 0) sinv[qi] = 1.0f / s;
    }
    __syncthreads();

    // pass 2: AV (vectorized)
    {
        const int qiA = warp * 2, qiB = qiA + 1;
        const int jsub = lane >> 3, dq = lane & 7;
        float4 a0 = make_float4(0, 0, 0, 0), a1 = make_float4(0, 0, 0, 0);
        const float4* vb = (const float4*)(v + h * DK + dq * 4);
        const float* spA = sp + qiA * L;
        const float* spB = sp + qiB * L;
        for (int j = 0; j < L; j += 4) {
            float4 vv = vb[(size_t)(j + jsub) * (D / 4)];
            float sA = spA[j + jsub], sB = spB[j + jsub];
            a0.x += sA * vv.x; a0.y += sA * vv.y; a0.z += sA * vv.z; a0.w += sA * vv.w;
            a1.x += sB * vv.x; a1.y += sB * vv.y; a1.z += sB * vv.z; a1.w += sB * vv.w;
        }
#pragma unroll
        for (int o = 8; o <= 16; o <<= 1) {
            a0.x += __shfl_xor_sync(0xffffffffu, a0.x, o);
            a0.y += __shfl_xor_sync(0xffffffffu, a0.y, o);
            a0.z += __shfl_xor_sync(0xffffffffu, a0.z, o);
            a0.w += __shfl_xor_sync(0xffffffffu, a0.w, o);
            a1.x += __shfl_xor_sync(0xffffffffu, a1.x, o);
            a1.y += __shfl_xor_sync(0xffffffffu, a1.y, o);
            a1.z += __shfl_xor_sync(0xffffffffu, a1.z, o);
            a1.w += __shfl_xor_sync(0xffffffffu, a1.w, o);
        }
        if (jsub == 0) {
            float iA = sinv[qiA], iB = sinv[qiB];
            float4 oA = make_float4(a0.x * iA, a0.y * iA, a0.z * iA, a0.w * iA);
            float4 oB = make_float4(a1.x * iB, a1.y * iB, a1.z * iB, a1.w * iB);
            *(float4*)(out + (size_t)(i0 + qiA) * D + h * DK + dq * 4) = oA;
            *(float4*)(out + (size_t)(i0 + qiB) * D + h * DK + dq * 4) = oB;
        }
    }
}

// ---------------- E1 ----------------
__global__ void e1_kernel(const float* __restrict__ rp, const float* __restrict__ W1,
                          const float* __restrict__ b1, float* __restrict__ E1) {
    int b = blockIdx.x;
    int d = threadIdx.x;
    float s = b1[d];
    for (int c = 0; c < D; c++) s += rp[b * D + c] * W1[c * D + d];
    E1[b * D + d] = s;
}

// ---------------- tf32 helpers (pair head) ----------------
__device__ __forceinline__ unsigned f2tf32(float x) {
    unsigned r;
    asm("cvt.rna.tf32.f32 %0, %1;" : "=r"(r) : "f"(x));
    return r;
}

__device__ __forceinline__ void mma_tf32(float* c, const unsigned* a, unsigned b0, unsigned b1) {
    asm volatile(
        "mma.sync.aligned.m16n8k8.row.col.f32.tf32.tf32.f32 "
        "{%0,%1,%2,%3}, {%4,%5,%6,%7}, {%8,%9}, {%0,%1,%2,%3};"
        : "+f"(c[0]), "+f"(c[1]), "+f"(c[2]), "+f"(c[3])
        : "r"(a[0]), "r"(a[1]), "r"(a[2]), "r"(a[3]), "r"(b0), "r"(b1));
}

__global__ void w1t_kernel(const float* __restrict__ W1, unsigned* __restrict__ W1t) {
    int t = blockIdx.x * 256 + threadIdx.x;
    W1t[t] = f2tf32(W1[t]);
}

// ---------------- pair head: tf32 HMMA, 1024 threads (unchanged) -----------
#define TI 4
#define TJ 32
#define PAD_A 36
#define PAD_B 264
#define PAD_E 260
#define AS_STRIDE (128 * PAD_A)
#define WS_STRIDE (32 * PAD_B)
#define PAIR_SMEM ((1024 + 512 + 2048 + NB * PAD_E + 2 * AS_STRIDE + 2 * WS_STRIDE) * 4)

__global__ void __launch_bounds__(1024, 1)
pair_tc2_kernel(const float* __restrict__ pq, const float* __restrict__ pk,
                const unsigned* __restrict__ W1t, const float* __restrict__ E1,
                const float* __restrict__ W2, const float* __restrict__ b2,
                const int* __restrict__ bucket, float* __restrict__ out) {
    extern __shared__ unsigned char smraw[];
    float*    qs  = (float*)smraw;
    float*    w2s = qs + 1024;
    float*    red = w2s + 512;
    float*    E1s = red + 2048;
    unsigned* As  = (unsigned*)(E1s + NB * PAD_E);
    unsigned* Ws  = As + 2 * AS_STRIDE;

    const int i0 = blockIdx.y * TI;
    const int j0 = blockIdx.x * TJ;
    const int tid = threadIdx.x;
    const int lane = tid & 31, warp = tid >> 5;
    const int gid = lane >> 2, tig = lane & 3;
    const int wm = warp >> 3;
    const int wn = warp & 7;

    if (tid < 256) ((float4*)qs)[tid] = ((const float4*)(pq + (size_t)i0 * D))[tid];
    if (tid < 512) w2s[tid] = W2[tid];
#pragma unroll
    for (int t = 0; t < 4; t++) {
        int idx = tid + t * 1024;
        int b = idx >> 6, d4 = (idx & 63) << 2;
        *(float4*)&E1s[b * PAD_E + d4] = *(const float4*)&E1[b * D + d4];
    }

    float acc[2][4][4] = {};

    const int pfill = tid >> 3;
    const int ccb = (tid & 7) * 4;
    const int ilf = pfill >> 5, jlf = pfill & 31;
    const float* pkrow = pk + (size_t)(j0 + jlf) * D;
    const float* qsrow = qs + ilf * D;
    const int wr0 = tid >> 6, wc0 = (tid & 63) << 2;

#pragma unroll
    for (int t = 0; t < 2; t++) {
        int row = wr0 + t * 16;
        *(uint4*)(Ws + row * PAD_B + wc0) = *(const uint4*)(W1t + (size_t)row * D + wc0);
    }
    __syncthreads();
    {
        float4 kv = *(const float4*)(pkrow + ccb);
        float4 qv = *(const float4*)(qsrow + ccb);
        uint4 o;
        o.x = f2tf32(kv.x * qv.x);
        o.y = f2tf32(kv.y * qv.y);
        o.z = f2tf32(kv.z * qv.z);
        o.w = f2tf32(kv.w * qv.w);
        *(uint4*)(As + pfill * PAD_A + ccb) = o;
    }
    __syncthreads();

    for (int ch = 0; ch < 8; ch++) {
        const int cur = ch & 1;
        const int k0n = (ch + 1) * 32;
        const unsigned* Ab = As + cur * AS_STRIDE;
        const unsigned* Wb = Ws + cur * WS_STRIDE;
#pragma unroll
        for (int kf = 0; kf < 4; kf++) {
            unsigned a[2][4];
#pragma unroll
            for (int mi = 0; mi < 2; mi++) {
                int R = wm * 32 + mi * 16;
                a[mi][0] = Ab[(R + gid) * PAD_A + kf * 8 + tig];
                a[mi][1] = Ab[(R + gid + 8) * PAD_A + kf * 8 + tig];
                a[mi][2] = Ab[(R + gid) * PAD_A + kf * 8 + tig + 4];
                a[mi][3] = Ab[(R + gid + 8) * PAD_A + kf * 8 + tig + 4];
            }
#pragma unroll
            for (int ni = 0; ni < 4; ni++) {
                unsigned b0 = Wb[(kf * 8 + tig) * PAD_B + wn * 32 + ni * 8 + gid];
                unsigned b1 = Wb[(kf * 8 + tig + 4) * PAD_B + wn * 32 + ni * 8 + gid];
                mma_tf32(acc[0][ni], a[0], b0, b1);
                mma_tf32(acc[1][ni], a[1], b0, b1);
            }
        }
        if (ch < 7) {
#pragma unroll
            for (int t = 0; t < 2; t++) {
                int row = wr0 + t * 16;
                *(uint4*)(Ws + (cur ^ 1) * WS_STRIDE + row * PAD_B + wc0) =
                    *(const uint4*)(W1t + (size_t)(k0n + row) * D + wc0);
            }
            float4 kv = *(const float4*)(pkrow + k0n + ccb);
            float4 qv = *(const float4*)(qsrow + k0n + ccb);
            uint4 o;
            o.x = f2tf32(kv.x * qv.x);
            o.y = f2tf32(kv.y * qv.y);
            o.z = f2tf32(kv.z * qv.z);
            o.w = f2tf32(kv.w * qv.w);
            *(uint4*)(As + (cur ^ 1) * AS_STRIDE + pfill * PAD_A + ccb) = o;
        }
        __syncthreads();
    }

    const float2* w2f = (const float2*)w2s;
#pragma unroll
    for (int mi = 0; mi < 2; mi++) {
#pragma unroll
        for (int half = 0; half < 2; half++) {
            int pl = wm * 32 + mi * 16 + gid + half * 8;
            int il = pl >> 5, jl = pl & 31;
            const float* e1row = E1s + (size_t)bucket[(i0 + il) * L + (j0 + jl)] * PAD_E;
            float p0 = 0.f, p1 = 0.f;
#pragma unroll
            for (int ni = 0; ni < 4; ni++) {
#pragma unroll
                for (int col = 0; col < 2; col++) {
                    int d = wn * 32 + ni * 8 + tig * 2 + col;
                    float hv = fmaxf(acc[mi][ni][half * 2 + col] + e1row[d], 0.f);
                    float2 w2v = w2f[d];
                    p0 += hv * w2v.x;
                    p1 += hv * w2v.y;
                }
            }
            p0 += __shfl_xor_sync(0xffffffffu, p0, 1);
            p0 += __shfl_xor_sync(0xffffffffu, p0, 2);
            p1 += __shfl_xor_sync(0xffffffffu, p1, 1);
            p1 += __shfl_xor_sync(0xffffffffu, p1, 2);
            if (tig == 0) {
                red[(wn * 128 + pl) * 2]     = p0;
                red[(wn * 128 + pl) * 2 + 1] = p1;
            }
        }
    }
    __syncthreads();
    if (tid < 256) {
        int pl = tid >> 1, comp = tid & 1;
        int il = pl >> 5, jl = pl & 31;
        float s = 0.f;
#pragma unroll
        for (int g = 0; g < 8; g++) s += red[(g * 128 + pl) * 2 + comp];
        out[((long)(i0 + il) * L + (j0 + jl)) * 2 + comp] = s + b2[comp];
    }
}

// ---------------- host launch ----------------
extern "C" void kernel_launch(void* const* d_in, const int* in_sizes, int n_in,
                              void* d_out, int out_size) {
    const int*   seq      = (const int*)d_in[0];
    const float* tok_emb  = (const float*)d_in[1];
    const float* rp_emb   = (const float*)d_in[2];
    const float* wq       = (const float*)d_in[3];
    const float* wk       = (const float*)d_in[4];
    const float* wv       = (const float*)d_in[5];
    const float* wo       = (const float*)d_in[6];
    const float* ln1_s    = (const float*)d_in[7];
    const float* ln1_b    = (const float*)d_in[8];
    const float* ln2_s    = (const float*)d_in[9];
    const float* ln2_b    = (const float*)d_in[10];
    const float* ffn_w1   = (const float*)d_in[11];
    const float* ffn_b1   = (const float*)d_in[12];
    const float* ffn_w2   = (const float*)d_in[13];
    const float* ffn_b2   = (const float*)d_in[14];
    const float* lnf_s    = (const float*)d_in[15];
    const float* lnf_b    = (const float*)d_in[16];
    const float* pair_q_w = (const float*)d_in[17];
    const float* pair_q_b = (const float*)d_in[18];
    const float* pair_k_w = (const float*)d_in[19];
    const float* pair_k_b = (const float*)d_in[20];
    const float* pair_rp  = (const float*)d_in[21];
    const float* cls_w1   = (const float*)d_in[22];
    const float* cls_b1   = (const float*)d_in[23];
    const float* cls_w2   = (const float*)d_in[24];
    const float* cls_b2   = (const float*)d_in[25];
    float* out = (float*)d_out;

    float *x, *h, *q, *k, *v, *attn, *ff, *pq, *pk, *E1, *dummy, *relbias;
    unsigned* W1t;
    int* bucket;
    __nv_bfloat16 *wqh, *wql, *wkh, *wkl, *wvh, *wvl, *woh, *wol;
    __nv_bfloat16 *f1h, *f1l, *f2h, *f2l, *pqh, *pql, *pkh, *pkl;
    cudaGetSymbolAddress((void**)&x, g_x);
    cudaGetSymbolAddress((void**)&h, g_h);
    cudaGetSymbolAddress((void**)&q, g_q);
    cudaGetSymbolAddress((void**)&k, g_k);
    cudaGetSymbolAddress((void**)&v, g_v);
    cudaGetSymbolAddress((void**)&attn, g_attn);
    cudaGetSymbolAddress((void**)&ff, g_ff);
    cudaGetSymbolAddress((void**)&pq, g_pq);
    cudaGetSymbolAddress((void**)&pk, g_pk);
    cudaGetSymbolAddress((void**)&E1, g_E1);
    cudaGetSymbolAddress((void**)&W1t, g_W1t);
    cudaGetSymbolAddress((void**)&bucket, g_bucket);
    cudaGetSymbolAddress((void**)&relbias, g_relbias);
    cudaGetSymbolAddress((void**)&dummy, g_dummy);
    cudaGetSymbolAddress((void**)&wqh, g_wq_hi); cudaGetSymbolAddress((void**)&wql, g_wq_lo);
    cudaGetSymbolAddress((void**)&wkh, g_wk_hi); cudaGetSymbolAddress((void**)&wkl, g_wk_lo);
    cudaGetSymbolAddress((void**)&wvh, g_wv_hi); cudaGetSymbolAddress((void**)&wvl, g_wv_lo);
    cudaGetSymbolAddress((void**)&woh, g_wo_hi); cudaGetSymbolAddress((void**)&wol, g_wo_lo);
    cudaGetSymbolAddress((void**)&f1h, g_f1_hi); cudaGetSymbolAddress((void**)&f1l, g_f1_lo);
    cudaGetSymbolAddress((void**)&f2h, g_f2_hi); cudaGetSymbolAddress((void**)&f2l, g_f2_lo);
    cudaGetSymbolAddress((void**)&pqh, g_pqw_hi); cudaGetSymbolAddress((void**)&pql, g_pqw_lo);
    cudaGetSymbolAddress((void**)&pkh, g_pkw_hi); cudaGetSymbolAddress((void**)&pkl, g_pkw_lo);

    cudaFuncSetAttribute(attn3_kernel, cudaFuncAttributeMaxDynamicSharedMemorySize, ATTN_SMEM);
    cudaFuncSetAttribute(pair_tc2_kernel, cudaFuncAttributeMaxDynamicSharedMemorySize, PAIR_SMEM);

    const int nqk = NLAYER * D * D;
    const int nf1 = NLAYER * D * DFF;
    const int nf2 = NLAYER * DFF * D;

    // ncu window profiles launch #4 -> attention v3 probe (96-block wave).
    bucket_kernel<<<(L * L + 255) / 256, 256>>>(bucket);                             // 1
    embed_kernel<<<L, D>>>(seq, tok_emb, x);                                         // 2
    relbias_kernel<<<(H * 1536 + 255) / 256, 256>>>(rp_emb, relbias);                // 3
    attn3_kernel<<<dim3(24, 4), 256, ATTN_SMEM>>>(q, k, v, relbias, dummy);          // 4 (PROBE)
    presplit_kernel<<<(nf1 + 255) / 256, 256>>>(ffn_w1, f1h, f1l, D, DFF, nf1);
    presplit_kernel<<<(nqk + 255) / 256, 256>>>(wq, wqh, wql, D, D, nqk);
    presplit_kernel<<<(nqk + 255) / 256, 256>>>(wk, wkh, wkl, D, D, nqk);
    presplit_kernel<<<(nqk + 255) / 256, 256>>>(wv, wvh, wvl, D, D, nqk);
    presplit_kernel<<<(nqk + 255) / 256, 256>>>(wo, woh, wol, D, D, nqk);
    presplit_kernel<<<(nf2 + 255) / 256, 256>>>(ffn_w2, f2h, f2l, DFF, D, nf2);
    presplit_kernel<<<(D * D + 255) / 256, 256>>>(pair_q_w, pqh, pql, D, D, D * D);
    presplit_kernel<<<(D * D + 255) / 256, 256>>>(pair_k_w, pkh, pkl, D, D, D * D);
    e1_kernel<<<NB, D>>>(pair_rp, cls_w1, cls_b1, E1);
    w1t_kernel<<<D * D / 256, 256>>>(cls_w1, W1t);

    dim3 gqkv(D / 64, L / 64, 3);
    dim3 g256(D / 64, L / 64);
    dim3 gff1(DFF / 64, L / 64);
    dim3 gpqpk(D / 64, L / 64, 2);

    for (int layer = 0; layer < NLAYER; layer++) {
        ln_kernel<<<L, D>>>(x, ln1_s + layer * D, ln1_b + layer * D, h);
        hgemm_qkv_kernel<<<gqkv, 256>>>(h, layer, q, k, v);
        attn3_kernel<<<dim3(L / QT, H), 256, ATTN_SMEM>>>(q, k, v, relbias, attn);
        hgemm_kernel<4><<<g256, 256>>>(attn, woh + (size_t)layer * D * D,
                                       wol + (size_t)layer * D * D, x,
                                       nullptr, x, L, D, D);
        ln_kernel<<<L, D>>>(x, ln2_s + layer * D, ln2_b + layer * D, h);
        hgemm_kernel<2><<<gff1, 256>>>(h, f1h + (size_t)layer * D * DFF,
                                       f1l + (size_t)layer * D * DFF, ff,
                                       ffn_b1 + layer * DFF, nullptr, L, DFF, D);
        hgemm_kernel<3><<<g256, 256>>>(ff, f2h + (size_t)layer * DFF * D,
                                       f2l + (size_t)layer * DFF * D, x,
                                       ffn_b2 + layer * D, x, L, D, DFF);
    }

    ln_kernel<<<L, D>>>(x, lnf_s, lnf_b, h);
    hgemm_pqpk_kernel<<<gpqpk, 256>>>(h, pair_q_b, pair_k_b, pq, pk);

    pair_tc2_kernel<<<dim3(L / TJ, L / TI), 1024, PAIR_SMEM>>>(
        pq, pk, W1t, E1, cls_w2, cls_b2, bucket, out);
}

// round 13
// speedup vs baseline: 1.5798x; 1.5798x over previous
#include <cuda_runtime.h>
#include <cuda_bf16.h>
#include <math.h>

#define L 768
#define D 256
#define H 8
#define DK 32
#define DFF 1024
#define NB 64
#define NLAYER 8

// ---------------- device scratch ----------------
__device__ float g_x[L * D];
__device__ float g_h[L * D];
__device__ float g_q[L * D];
__device__ float g_k[L * D];
__device__ float g_v[L * D];
__device__ float g_attn[L * D];
__device__ float g_ff[L * DFF];
__device__ float g_pq[L * D];
__device__ float g_pk[L * D];
__device__ float g_E1[NB * D];
__device__ unsigned g_W1t[D * D];
__device__ int   g_bucket[L * L];
__device__ float g_relbias[H * 1536];

__device__ __nv_bfloat16 g_wq_hi[NLAYER * D * D], g_wq_lo[NLAYER * D * D];
__device__ __nv_bfloat16 g_wk_hi[NLAYER * D * D], g_wk_lo[NLAYER * D * D];
__device__ __nv_bfloat16 g_wv_hi[NLAYER * D * D], g_wv_lo[NLAYER * D * D];
__device__ __nv_bfloat16 g_wo_hi[NLAYER * D * D], g_wo_lo[NLAYER * D * D];
__device__ __nv_bfloat16 g_f1_hi[NLAYER * D * DFF], g_f1_lo[NLAYER * D * DFF];
__device__ __nv_bfloat16 g_f2_hi[NLAYER * DFF * D], g_f2_lo[NLAYER * DFF * D];
__device__ __nv_bfloat16 g_pqw_hi[D * D], g_pqw_lo[D * D];
__device__ __nv_bfloat16 g_pkw_hi[D * D], g_pkw_lo[D * D];

// ---------------- helpers ----------------
__device__ __forceinline__ unsigned smem_u32(const void* p) {
    unsigned a;
    asm("{ .reg .u64 t; cvta.to.shared.u64 t, %1; cvt.u32.u64 %0, t; }" : "=r"(a) : "l"(p));
    return a;
}
__device__ __forceinline__ void cp_async16(unsigned saddr, const void* gptr) {
    asm volatile("cp.async.cg.shared.global [%0], [%1], 16;" :: "r"(saddr), "l"(gptr));
}
#define CP_COMMIT() asm volatile("cp.async.commit_group;")
#define CP_WAIT0()  asm volatile("cp.async.wait_group 0;")

// ---------------- bucket table (pair head epilogue) ----------------
__global__ void bucket_kernel(int* __restrict__ bucket) {
    int idx = blockIdx.x * blockDim.x + threadIdx.x;
    if (idx >= L * L) return;
    int i = idx / L, j = idx % L;
    int rel = i - j;
    int ret = (rel < 0) ? 32 : 0;
    int arp = abs(rel);
    int val;
    if (arp < 16) {
        val = arp;
    } else {
        float safe = (float)(arp < 1 ? 1 : arp);
        float t = logf(safe / 16.0f) / 2.7725887f * 16.0f;
        int vil = 16 + (int)t;
        val = vil < 31 ? vil : 31;
    }
    bucket[idx] = ret + val;
}

__global__ void relbias_kernel(const float* __restrict__ rp_emb,
                               float* __restrict__ relbias) {
    int idx = blockIdx.x * 256 + threadIdx.x;
    if (idx >= H * 1536) return;
    int h = idx / 1536, r = idx % 1536;
    int rel = r - 768;
    int ret = (rel < 0) ? 32 : 0;
    int arp = abs(rel);
    int val;
    if (arp < 16) {
        val = arp;
    } else {
        float safe = (float)(arp < 1 ? 1 : arp);
        float t = logf(safe / 16.0f) / 2.7725887f * 16.0f;
        int vil = 16 + (int)t;
        val = vil < 31 ? vil : 31;
    }
    relbias[idx] = rp_emb[(ret + val) * H + h];
}

// ---------------- embedding ----------------
__global__ void embed_kernel(const int* __restrict__ seq,
                             const float* __restrict__ tok_emb,
                             float* __restrict__ x) {
    int l = blockIdx.x;
    int d = threadIdx.x;
    x[l * D + d] = tok_emb[seq[l] * D + d];
}

// ---------------- layernorm ----------------
__global__ void ln_kernel(const float* __restrict__ x,
                          const float* __restrict__ s,
                          const float* __restrict__ b,
                          float* __restrict__ out) {
    int row = blockIdx.x;
    int tid = threadIdx.x;
    float val = x[row * D + tid];
    float s1 = val, s2 = val * val;
#pragma unroll
    for (int o = 16; o > 0; o >>= 1) {
        s1 += __shfl_xor_sync(0xffffffffu, s1, o);
        s2 += __shfl_xor_sync(0xffffffffu, s2, o);
    }
    __shared__ float r1[8], r2[8];
    if ((tid & 31) == 0) { r1[tid >> 5] = s1; r2[tid >> 5] = s2; }
    __syncthreads();
    float t1 = 0.f, t2 = 0.f;
#pragma unroll
    for (int w = 0; w < 8; w++) { t1 += r1[w]; t2 += r2[w]; }
    float m = t1 * (1.0f / D);
    float var = t2 * (1.0f / D) - m * m;
    out[row * D + tid] = (val - m) * rsqrtf(var + 1e-5f) * s[tid] + b[tid];
}

// ---------------- presplit v2: coalesced smem-tile transpose ----------------
// W [l][k][n] fp32 -> hiT/loT [l][n][k] bf16. Block = one 32x32 tile.
__global__ void presplit2_kernel(const float* __restrict__ W,
                                 __nv_bfloat16* __restrict__ hiT,
                                 __nv_bfloat16* __restrict__ loT,
                                 int K, int N) {
    __shared__ float tile[32][33];
    const int tiles_n = N >> 5;
    const int tk = blockIdx.x / tiles_n, tn = blockIdx.x % tiles_n;
    const int l = blockIdx.y;
    const float* Wl = W + (size_t)l * K * N;
    __nv_bfloat16* hl = hiT + (size_t)l * K * N;
    __nv_bfloat16* ll = loT + (size_t)l * K * N;
    const int r = threadIdx.x >> 5, c = threadIdx.x & 31;
#pragma unroll
    for (int p = 0; p < 4; p++)
        tile[r + p * 8][c] = Wl[(size_t)(tk * 32 + r + p * 8) * N + tn * 32 + c];
    __syncthreads();
#pragma unroll
    for (int p = 0; p < 4; p++) {
        int n = tn * 32 + r + p * 8;
        int kk = tk * 32 + c;
        float a = tile[c][r + p * 8];
        __nv_bfloat16 hh = __float2bfloat16(a);
        hl[(size_t)n * K + kk] = hh;
        ll[(size_t)n * K + kk] = __float2bfloat16(a - __bfloat162float(hh));
    }
}

// ---------------- bf16-split HMMA GEMM, double-buffered + cp.async ---------
__device__ __forceinline__ float gelu_exact(float x) {
    return 0.5f * x * (1.0f + erff(x * 0.70710678118654752f));
}

__device__ __forceinline__ void mma_bf16(float* c, const unsigned* a, unsigned b0, unsigned b1) {
    asm volatile(
        "mma.sync.aligned.m16n8k16.row.col.f32.bf16.bf16.f32 "
        "{%0,%1,%2,%3}, {%4,%5,%6,%7}, {%8,%9}, {%0,%1,%2,%3};"
        : "+f"(c[0]), "+f"(c[1]), "+f"(c[2]), "+f"(c[3])
        : "r"(a[0]), "r"(a[1]), "r"(a[2]), "r"(a[3]), "r"(b0), "r"(b1));
}

__device__ __forceinline__ unsigned packsplit(float a, float b, unsigned& lo) {
    __nv_bfloat16 ha = __float2bfloat16(a), hb = __float2bfloat16(b);
    __nv_bfloat16 la = __float2bfloat16(a - __bfloat162float(ha));
    __nv_bfloat16 lb = __float2bfloat16(b - __bfloat162float(hb));
    lo = (unsigned)__bfloat16_as_ushort(la) | ((unsigned)__bfloat16_as_ushort(lb) << 16);
    return (unsigned)__bfloat16_as_ushort(ha) | ((unsigned)__bfloat16_as_ushort(hb) << 16);
}

#define HPAD 20

template <int EPI>
__device__ __forceinline__ void hgemm_body(
    const float* __restrict__ A, const __nv_bfloat16* __restrict__ BhiT,
    const __nv_bfloat16* __restrict__ BloT, float* __restrict__ C,
    const float* __restrict__ bias, const float* __restrict__ res,
    int M, int N, int K, int bx, int by)
{
    __shared__ unsigned sAhi[2][64 * HPAD], sAlo[2][64 * HPAD];
    __shared__ unsigned sBhi[2][64 * HPAD], sBlo[2][64 * HPAD];
    const int tid = threadIdx.x;
    const int lane = tid & 31, warp = tid >> 5;
    const int gid = lane >> 2, tig = lane & 3;
    const int wm = warp >> 2, wn = warp & 3;
    const int row0 = by * 64, col0 = bx * 64;

    float acc[2][2][4] = {};

    const int arow = tid >> 3;
    const int akq  = (tid & 7) * 4;
    const int bn   = tid >> 2;
    const int bq   = (tid & 3) * 4;

    const float* Ap0 = A + (size_t)(row0 + arow) * K + akq;
    const float* Ap1 = A + (size_t)(row0 + arow + 32) * K + akq;
    const __nv_bfloat16* Bph = BhiT + (size_t)(col0 + bn) * K + bq * 2;
    const __nv_bfloat16* Bpl = BloT + (size_t)(col0 + bn) * K + bq * 2;
    unsigned aBhi[2], aBlo[2];
    aBhi[0] = smem_u32(&sBhi[0][bn * HPAD + bq]);
    aBhi[1] = smem_u32(&sBhi[1][bn * HPAD + bq]);
    aBlo[0] = smem_u32(&sBlo[0][bn * HPAD + bq]);
    aBlo[1] = smem_u32(&sBlo[1][bn * HPAD + bq]);

    // ---- initial stage into buffer 0 ----
    cp_async16(aBhi[0], Bph);
    cp_async16(aBlo[0], Bpl);
    CP_COMMIT();
    {
        float4 a0 = *(const float4*)Ap0;
        float4 a1 = *(const float4*)Ap1;
        unsigned lo01, lo23;
        unsigned hi01 = packsplit(a0.x, a0.y, lo01);
        unsigned hi23 = packsplit(a0.z, a0.w, lo23);
        uint2 hv; hv.x = hi01; hv.y = hi23;
        uint2 lv; lv.x = lo01; lv.y = lo23;
        *(uint2*)&sAhi[0][arow * HPAD + (akq >> 1)] = hv;
        *(uint2*)&sAlo[0][arow * HPAD + (akq >> 1)] = lv;
        hi01 = packsplit(a1.x, a1.y, lo01);
        hi23 = packsplit(a1.z, a1.w, lo23);
        hv.x = hi01; hv.y = hi23;
        lv.x = lo01; lv.y = lo23;
        *(uint2*)&sAhi[0][(arow + 32) * HPAD + (akq >> 1)] = hv;
        *(uint2*)&sAlo[0][(arow + 32) * HPAD + (akq >> 1)] = lv;
    }
    CP_WAIT0();
    __syncthreads();

    const int nch = K / 32;
    for (int ch = 0; ch < nch; ch++) {
        const int cur = ch & 1, nxt = cur ^ 1;
        const bool pf = (ch + 1 < nch);
        float4 a0pre, a1pre;
        if (pf) {
            const int k0n = (ch + 1) * 32;
            cp_async16(aBhi[nxt], Bph + k0n);
            cp_async16(aBlo[nxt], Bpl + k0n);
            CP_COMMIT();
            a0pre = *(const float4*)(Ap0 + k0n);
            a1pre = *(const float4*)(Ap1 + k0n);
        }
        // ---- mma on buffer cur ----
        const unsigned* bAhi = sAhi[cur];
        const unsigned* bAlo = sAlo[cur];
        const unsigned* bBhi = sBhi[cur];
        const unsigned* bBlo = sBlo[cur];
#pragma unroll
        for (int ks = 0; ks < 2; ks++) {
            const int kb = ks * 8;
            unsigned ahi[2][4], alo[2][4];
#pragma unroll
            for (int mi = 0; mi < 2; mi++) {
                int R = wm * 32 + mi * 16;
                ahi[mi][0] = bAhi[(R + gid) * HPAD + kb + tig];
                ahi[mi][1] = bAhi[(R + gid + 8) * HPAD + kb + tig];
                ahi[mi][2] = bAhi[(R + gid) * HPAD + kb + tig + 4];
                ahi[mi][3] = bAhi[(R + gid + 8) * HPAD + kb + tig + 4];
                alo[mi][0] = bAlo[(R + gid) * HPAD + kb + tig];
                alo[mi][1] = bAlo[(R + gid + 8) * HPAD + kb + tig];
                alo[mi][2] = bAlo[(R + gid) * HPAD + kb + tig + 4];
                alo[mi][3] = bAlo[(R + gid + 8) * HPAD + kb + tig + 4];
            }
#pragma unroll
            for (int ni = 0; ni < 2; ni++) {
                int nc = wn * 16 + ni * 8;
                unsigned bh0 = bBhi[(nc + gid) * HPAD + kb + tig];
                unsigned bh1 = bBhi[(nc + gid) * HPAD + kb + tig + 4];
                unsigned bl0 = bBlo[(nc + gid) * HPAD + kb + tig];
                unsigned bl1 = bBlo[(nc + gid) * HPAD + kb + tig + 4];
#pragma unroll
                for (int mi = 0; mi < 2; mi++) {
                    mma_bf16(acc[mi][ni], ahi[mi], bh0, bh1);
                    mma_bf16(acc[mi][ni], ahi[mi], bl0, bl1);
                    mma_bf16(acc[mi][ni], alo[mi], bh0, bh1);
                }
            }
        }
        if (pf) {
            unsigned lo01, lo23;
            unsigned hi01 = packsplit(a0pre.x, a0pre.y, lo01);
            unsigned hi23 = packsplit(a0pre.z, a0pre.w, lo23);
            uint2 hv; hv.x = hi01; hv.y = hi23;
            uint2 lv; lv.x = lo01; lv.y = lo23;
            *(uint2*)&sAhi[nxt][arow * HPAD + (akq >> 1)] = hv;
            *(uint2*)&sAlo[nxt][arow * HPAD + (akq >> 1)] = lv;
            hi01 = packsplit(a1pre.x, a1pre.y, lo01);
            hi23 = packsplit(a1pre.z, a1pre.w, lo23);
            hv.x = hi01; hv.y = hi23;
            lv.x = lo01; lv.y = lo23;
            *(uint2*)&sAhi[nxt][(arow + 32) * HPAD + (akq >> 1)] = hv;
            *(uint2*)&sAlo[nxt][(arow + 32) * HPAD + (akq >> 1)] = lv;
            CP_WAIT0();
        }
        __syncthreads();
    }

#pragma unroll
    for (int mi = 0; mi < 2; mi++) {
#pragma unroll
        for (int ni = 0; ni < 2; ni++) {
            int m0 = row0 + wm * 32 + mi * 16 + gid;
            int n = col0 + wn * 16 + ni * 8 + tig * 2;
            float v0 = acc[mi][ni][0], v1 = acc[mi][ni][1];
            float v2 = acc[mi][ni][2], v3 = acc[mi][ni][3];
            if (EPI == 1 || EPI == 2 || EPI == 3) {
                float2 bb = *(const float2*)&bias[n];
                v0 += bb.x; v1 += bb.y; v2 += bb.x; v3 += bb.y;
            }
            if (EPI == 2) {
                v0 = gelu_exact(v0); v1 = gelu_exact(v1);
                v2 = gelu_exact(v2); v3 = gelu_exact(v3);
            }
            if (EPI == 3 || EPI == 4) {
                float2 r0 = *(const float2*)&res[(size_t)m0 * N + n];
                float2 r1 = *(const float2*)&res[(size_t)(m0 + 8) * N + n];
                v0 += r0.x; v1 += r0.y; v2 += r1.x; v3 += r1.y;
            }
            float2 o0; o0.x = v0; o0.y = v1;
            float2 o1; o1.x = v2; o1.y = v3;
            *(float2*)&C[(size_t)m0 * N + n] = o0;
            *(float2*)&C[(size_t)(m0 + 8) * N + n] = o1;
        }
    }
}

template <int EPI>
__global__ void __launch_bounds__(256, 3)
hgemm_kernel(const float* __restrict__ A, const __nv_bfloat16* __restrict__ BhiT,
             const __nv_bfloat16* __restrict__ BloT, float* __restrict__ C,
             const float* __restrict__ bias, const float* __restrict__ res,
             int M, int N, int K) {
    hgemm_body<EPI>(A, BhiT, BloT, C, bias, res, M, N, K, blockIdx.x, blockIdx.y);
}

__global__ void __launch_bounds__(256, 3)
hgemm_qkv_kernel(const float* __restrict__ A, int layer,
                 float* __restrict__ q, float* __restrict__ k, float* __restrict__ v) {
    const size_t off = (size_t)layer * D * D;
    const __nv_bfloat16 *bh, *bl;
    float* C;
    if (blockIdx.z == 0)      { bh = g_wq_hi + off; bl = g_wq_lo + off; C = q; }
    else if (blockIdx.z == 1) { bh = g_wk_hi + off; bl = g_wk_lo + off; C = k; }
    else                      { bh = g_wv_hi + off; bl = g_wv_lo + off; C = v; }
    hgemm_body<0>(A, bh, bl, C, nullptr, nullptr, L, D, D, blockIdx.x, blockIdx.y);
}

__global__ void __launch_bounds__(256, 3)
hgemm_pqpk_kernel(const float* __restrict__ A,
                  const float* __restrict__ bq, const float* __restrict__ bk,
                  float* __restrict__ pq, float* __restrict__ pk) {
    const __nv_bfloat16 *bh, *bl;
    const float* bias;
    float* C;
    if (blockIdx.z == 0) { bh = g_pqw_hi; bl = g_pqw_lo; bias = bq; C = pq; }
    else                 { bh = g_pkw_hi; bl = g_pkw_lo; bias = bk; C = pk; }
    hgemm_body<1>(A, bh, bl, C, bias, nullptr, L, D, D, blockIdx.x, blockIdx.y);
}

// ---------------- attention v4: MLP-batched pass2, unrolled pass1 ----------
#define QT 16
#define ATTN_SMEM ((QT * DK + 784 + QT * L + QT) * 4)
__global__ void __launch_bounds__(256, 3)
attn3_kernel(const float* __restrict__ q, const float* __restrict__ k,
             const float* __restrict__ v, const float* __restrict__ relbias,
             float* __restrict__ out) {
    extern __shared__ unsigned char smraw[];
    float* sq = (float*)smraw;
    float* sbias = sq + QT * DK;
    float* sp = sbias + 784;
    float* sinv = sp + QT * L;
    const int i0 = blockIdx.x * QT;
    const int h = blockIdx.y;
    const int tid = threadIdx.x;
    const float invscale = 0.17677669529663687f;

    for (int t = tid; t < QT * DK; t += 256)
        sq[t] = q[(i0 + (t >> 5)) * D + h * DK + (t & 31)];
    for (int t = tid; t < 783; t += 256)
        sbias[t] = relbias[h * 1536 + i0 + 1 + t];
    __syncthreads();

    // pass 1: 3 unrolled j-strips per thread
#pragma unroll
    for (int it = 0; it < 3; it++) {
        int j = tid + it * 256;
        float4 kv[8];
        const float4* kr = (const float4*)(k + (size_t)j * D + h * DK);
#pragma unroll
        for (int t = 0; t < 8; t++) kv[t] = kr[t];
        float dot[QT];
#pragma unroll
        for (int qi = 0; qi < QT; qi++) dot[qi] = 0.f;
#pragma unroll
        for (int t = 0; t < 8; t++) {
#pragma unroll
            for (int qi = 0; qi < QT; qi++) {
                float4 qv = *(const float4*)(sq + qi * DK + t * 4);
                dot[qi] += qv.x * kv[t].x + qv.y * kv[t].y + qv.z * kv[t].z + qv.w * kv[t].w;
            }
        }
#pragma unroll
        for (int qi = 0; qi < QT; qi++)
            sp[qi * L + j] = dot[qi] * invscale + sbias[qi - j + 767];
    }
    __syncthreads();

    const int warp = tid >> 5, lane = tid & 31;
#pragma unroll
    for (int qq = 0; qq < 2; qq++) {
        int qi = warp * 2 + qq;
        float m = -1e30f;
        for (int j = lane; j < L; j += 32) m = fmaxf(m, sp[qi * L + j]);
#pragma unroll
        for (int o = 16; o > 0; o >>= 1) m = fmaxf(m, __shfl_xor_sync(0xffffffffu, m, o));
        float s = 0.f;
        for (int j = lane; j < L; j += 32) {
            float e = expf(sp[qi * L + j] - m);
            sp[qi * L + j] = e;
            s += e;
        }
#pragma unroll
        for (int o = 16; o > 0; o >>= 1) s += __shfl_xor_sync(0xffffffffu, s, o);
        if (lane == 0) sinv[qi] = 1.0f / s;
    }
    __syncthreads();

    // pass 2: AV with MLP=4 explicit load batches
    {
        const int qiA = warp * 2, qiB = qiA + 1;
        const int jsub = lane >> 3, dq = lane & 7;
        float4 a0 = make_float4(0, 0, 0, 0), a1 = make_float4(0, 0, 0, 0);
        const float4* vb = (const float4*)(v + h * DK + dq * 4);
        const float* spA = sp + qiA * L;
        const float* spB = sp + qiB * L;
#pragma unroll 3
        for (int j = 0; j < L; j += 16) {
            float4 vv[4];
            float sA[4], sB[4];
#pragma unroll
            for (int t = 0; t < 4; t++) {
                int jj = j + t * 4 + jsub;
                vv[t] = vb[(size_t)jj * (D / 4)];
                sA[t] = spA[jj];
                sB[t] = spB[jj];
            }
#pragma unroll
            for (int t = 0; t < 4; t++) {
                a0.x += sA[t] * vv[t].x; a0.y += sA[t] * vv[t].y;
                a0.z += sA[t] * vv[t].z; a0.w += sA[t] * vv[t].w;
                a1.x += sB[t] * vv[t].x; a1.y += sB[t] * vv[t].y;
                a1.z += sB[t] * vv[t].z; a1.w += sB[t] * vv[t].w;
            }
        }
#pragma unroll
        for (int o = 8; o <= 16; o <<= 1) {
            a0.x += __shfl_xor_sync(0xffffffffu, a0.x, o);
            a0.y += __shfl_xor_sync(0xffffffffu, a0.y, o);
            a0.z += __shfl_xor_sync(0xffffffffu, a0.z, o);
            a0.w += __shfl_xor_sync(0xffffffffu, a0.w, o);
            a1.x += __shfl_xor_sync(0xffffffffu, a1.x, o);
            a1.y += __shfl_xor_sync(0xffffffffu, a1.y, o);
            a1.z += __shfl_xor_sync(0xffffffffu, a1.z, o);
            a1.w += __shfl_xor_sync(0xffffffffu, a1.w, o);
        }
        if (jsub == 0) {
            float iA = sinv[qiA], iB = sinv[qiB];
            float4 oA = make_float4(a0.x * iA, a0.y * iA, a0.z * iA, a0.w * iA);
            float4 oB = make_float4(a1.x * iB, a1.y * iB, a1.z * iB, a1.w * iB);
            *(float4*)(out + (size_t)(i0 + qiA) * D + h * DK + dq * 4) = oA;
            *(float4*)(out + (size_t)(i0 + qiB) * D + h * DK + dq * 4) = oB;
        }
    }
}

// ---------------- E1 ----------------
__global__ void e1_kernel(const float* __restrict__ rp, const float* __restrict__ W1,
                          const float* __restrict__ b1, float* __restrict__ E1) {
    int b = blockIdx.x;
    int d = threadIdx.x;
    float s = b1[d];
    for (int c = 0; c < D; c++) s += rp[b * D + c] * W1[c * D + d];
    E1[b * D + d] = s;
}

// ---------------- tf32 helpers (pair head) ----------------
__device__ __forceinline__ unsigned f2tf32(float x) {
    unsigned r;
    asm("cvt.rna.tf32.f32 %0, %1;" : "=r"(r) : "f"(x));
    return r;
}

__device__ __forceinline__ void mma_tf32(float* c, const unsigned* a, unsigned b0, unsigned b1) {
    asm volatile(
        "mma.sync.aligned.m16n8k8.row.col.f32.tf32.tf32.f32 "
        "{%0,%1,%2,%3}, {%4,%5,%6,%7}, {%8,%9}, {%0,%1,%2,%3};"
        : "+f"(c[0]), "+f"(c[1]), "+f"(c[2]), "+f"(c[3])
        : "r"(a[0]), "r"(a[1]), "r"(a[2]), "r"(a[3]), "r"(b0), "r"(b1));
}

__global__ void w1t_kernel(const float* __restrict__ W1, unsigned* __restrict__ W1t) {
    int t = blockIdx.x * 256 + threadIdx.x;
    W1t[t] = f2tf32(W1[t]);
}

// ---------------- pair head: tf32 HMMA, 1024 threads (unchanged) -----------
#define TI 4
#define TJ 32
#define PAD_A 36
#define PAD_B 264
#define PAD_E 260
#define AS_STRIDE (128 * PAD_A)
#define WS_STRIDE (32 * PAD_B)
#define PAIR_SMEM ((1024 + 512 + 2048 + NB * PAD_E + 2 * AS_STRIDE + 2 * WS_STRIDE) * 4)

__global__ void __launch_bounds__(1024, 1)
pair_tc2_kernel(const float* __restrict__ pq, const float* __restrict__ pk,
                const unsigned* __restrict__ W1t, const float* __restrict__ E1,
                const float* __restrict__ W2, const float* __restrict__ b2,
                const int* __restrict__ bucket, float* __restrict__ out) {
    extern __shared__ unsigned char smraw[];
    float*    qs  = (float*)smraw;
    float*    w2s = qs + 1024;
    float*    red = w2s + 512;
    float*    E1s = red + 2048;
    unsigned* As  = (unsigned*)(E1s + NB * PAD_E);
    unsigned* Ws  = As + 2 * AS_STRIDE;

    const int i0 = blockIdx.y * TI;
    const int j0 = blockIdx.x * TJ;
    const int tid = threadIdx.x;
    const int lane = tid & 31, warp = tid >> 5;
    const int gid = lane >> 2, tig = lane & 3;
    const int wm = warp >> 3;
    const int wn = warp & 7;

    if (tid < 256) ((float4*)qs)[tid] = ((const float4*)(pq + (size_t)i0 * D))[tid];
    if (tid < 512) w2s[tid] = W2[tid];
#pragma unroll
    for (int t = 0; t < 4; t++) {
        int idx = tid + t * 1024;
        int b = idx >> 6, d4 = (idx & 63) << 2;
        *(float4*)&E1s[b * PAD_E + d4] = *(const float4*)&E1[b * D + d4];
    }

    float acc[2][4][4] = {};

    const int pfill = tid >> 3;
    const int ccb = (tid & 7) * 4;
    const int ilf = pfill >> 5, jlf = pfill & 31;
    const float* pkrow = pk + (size_t)(j0 + jlf) * D;
    const float* qsrow = qs + ilf * D;
    const int wr0 = tid >> 6, wc0 = (tid & 63) << 2;

#pragma unroll
    for (int t = 0; t < 2; t++) {
        int row = wr0 + t * 16;
        *(uint4*)(Ws + row * PAD_B + wc0) = *(const uint4*)(W1t + (size_t)row * D + wc0);
    }
    __syncthreads();
    {
        float4 kv = *(const float4*)(pkrow + ccb);
        float4 qv = *(const float4*)(qsrow + ccb);
        uint4 o;
        o.x = f2tf32(kv.x * qv.x);
        o.y = f2tf32(kv.y * qv.y);
        o.z = f2tf32(kv.z * qv.z);
        o.w = f2tf32(kv.w * qv.w);
        *(uint4*)(As + pfill * PAD_A + ccb) = o;
    }
    __syncthreads();

    for (int ch = 0; ch < 8; ch++) {
        const int cur = ch & 1;
        const int k0n = (ch + 1) * 32;
        const unsigned* Ab = As + cur * AS_STRIDE;
        const unsigned* Wb = Ws + cur * WS_STRIDE;
#pragma unroll
        for (int kf = 0; kf < 4; kf++) {
            unsigned a[2][4];
#pragma unroll
            for (int mi = 0; mi < 2; mi++) {
                int R = wm * 32 + mi * 16;
                a[mi][0] = Ab[(R + gid) * PAD_A + kf * 8 + tig];
                a[mi][1] = Ab[(R + gid + 8) * PAD_A + kf * 8 + tig];
                a[mi][2] = Ab[(R + gid) * PAD_A + kf * 8 + tig + 4];
                a[mi][3] = Ab[(R + gid + 8) * PAD_A + kf * 8 + tig + 4];
            }
#pragma unroll
            for (int ni = 0; ni < 4; ni++) {
                unsigned b0 = Wb[(kf * 8 + tig) * PAD_B + wn * 32 + ni * 8 + gid];
                unsigned b1 = Wb[(kf * 8 + tig + 4) * PAD_B + wn * 32 + ni * 8 + gid];
                mma_tf32(acc[0][ni], a[0], b0, b1);
                mma_tf32(acc[1][ni], a[1], b0, b1);
            }
        }
        if (ch < 7) {
#pragma unroll
            for (int t = 0; t < 2; t++) {
                int row = wr0 + t * 16;
                *(uint4*)(Ws + (cur ^ 1) * WS_STRIDE + row * PAD_B + wc0) =
                    *(const uint4*)(W1t + (size_t)(k0n + row) * D + wc0);
            }
            float4 kv = *(const float4*)(pkrow + k0n + ccb);
            float4 qv = *(const float4*)(qsrow + k0n + ccb);
            uint4 o;
            o.x = f2tf32(kv.x * qv.x);
            o.y = f2tf32(kv.y * qv.y);
            o.z = f2tf32(kv.z * qv.z);
            o.w = f2tf32(kv.w * qv.w);
            *(uint4*)(As + (cur ^ 1) * AS_STRIDE + pfill * PAD_A + ccb) = o;
        }
        __syncthreads();
    }

    const float2* w2f = (const float2*)w2s;
#pragma unroll
    for (int mi = 0; mi < 2; mi++) {
#pragma unroll
        for (int half = 0; half < 2; half++) {
            int pl = wm * 32 + mi * 16 + gid + half * 8;
            int il = pl >> 5, jl = pl & 31;
            const float* e1row = E1s + (size_t)bucket[(i0 + il) * L + (j0 + jl)] * PAD_E;
            float p0 = 0.f, p1 = 0.f;
#pragma unroll
            for (int ni = 0; ni < 4; ni++) {
#pragma unroll
                for (int col = 0; col < 2; col++) {
                    int d = wn * 32 + ni * 8 + tig * 2 + col;
                    float hv = fmaxf(acc[mi][ni][half * 2 + col] + e1row[d], 0.f);
                    float2 w2v = w2f[d];
                    p0 += hv * w2v.x;
                    p1 += hv * w2v.y;
                }
            }
            p0 += __shfl_xor_sync(0xffffffffu, p0, 1);
            p0 += __shfl_xor_sync(0xffffffffu, p0, 2);
            p1 += __shfl_xor_sync(0xffffffffu, p1, 1);
            p1 += __shfl_xor_sync(0xffffffffu, p1, 2);
            if (tig == 0) {
                red[(wn * 128 + pl) * 2]     = p0;
                red[(wn * 128 + pl) * 2 + 1] = p1;
            }
        }
    }
    __syncthreads();
    if (tid < 256) {
        int pl = tid >> 1, comp = tid & 1;
        int il = pl >> 5, jl = pl & 31;
        float s = 0.f;
#pragma unroll
        for (int g = 0; g < 8; g++) s += red[(g * 128 + pl) * 2 + comp];
        out[((long)(i0 + il) * L + (j0 + jl)) * 2 + comp] = s + b2[comp];
    }
}

// ---------------- host launch ----------------
extern "C" void kernel_launch(void* const* d_in, const int* in_sizes, int n_in,
                              void* d_out, int out_size) {
    const int*   seq      = (const int*)d_in[0];
    const float* tok_emb  = (const float*)d_in[1];
    const float* rp_emb   = (const float*)d_in[2];
    const float* wq       = (const float*)d_in[3];
    const float* wk       = (const float*)d_in[4];
    const float* wv       = (const float*)d_in[5];
    const float* wo       = (const float*)d_in[6];
    const float* ln1_s    = (const float*)d_in[7];
    const float* ln1_b    = (const float*)d_in[8];
    const float* ln2_s    = (const float*)d_in[9];
    const float* ln2_b    = (const float*)d_in[10];
    const float* ffn_w1   = (const float*)d_in[11];
    const float* ffn_b1   = (const float*)d_in[12];
    const float* ffn_w2   = (const float*)d_in[13];
    const float* ffn_b2   = (const float*)d_in[14];
    const float* lnf_s    = (const float*)d_in[15];
    const float* lnf_b    = (const float*)d_in[16];
    const float* pair_q_w = (const float*)d_in[17];
    const float* pair_q_b = (const float*)d_in[18];
    const float* pair_k_w = (const float*)d_in[19];
    const float* pair_k_b = (const float*)d_in[20];
    const float* pair_rp  = (const float*)d_in[21];
    const float* cls_w1   = (const float*)d_in[22];
    const float* cls_b1   = (const float*)d_in[23];
    const float* cls_w2   = (const float*)d_in[24];
    const float* cls_b2   = (const float*)d_in[25];
    float* out = (float*)d_out;

    float *x, *h, *q, *k, *v, *attn, *ff, *pq, *pk, *E1, *relbias;
    unsigned* W1t;
    int* bucket;
    __nv_bfloat16 *wqh, *wql, *wkh, *wkl, *wvh, *wvl, *woh, *wol;
    __nv_bfloat16 *f1h, *f1l, *f2h, *f2l, *pqh, *pql, *pkh, *pkl;
    cudaGetSymbolAddress((void**)&x, g_x);
    cudaGetSymbolAddress((void**)&h, g_h);
    cudaGetSymbolAddress((void**)&q, g_q);
    cudaGetSymbolAddress((void**)&k, g_k);
    cudaGetSymbolAddress((void**)&v, g_v);
    cudaGetSymbolAddress((void**)&attn, g_attn);
    cudaGetSymbolAddress((void**)&ff, g_ff);
    cudaGetSymbolAddress((void**)&pq, g_pq);
    cudaGetSymbolAddress((void**)&pk, g_pk);
    cudaGetSymbolAddress((void**)&E1, g_E1);
    cudaGetSymbolAddress((void**)&W1t, g_W1t);
    cudaGetSymbolAddress((void**)&bucket, g_bucket);
    cudaGetSymbolAddress((void**)&relbias, g_relbias);
    cudaGetSymbolAddress((void**)&wqh, g_wq_hi); cudaGetSymbolAddress((void**)&wql, g_wq_lo);
    cudaGetSymbolAddress((void**)&wkh, g_wk_hi); cudaGetSymbolAddress((void**)&wkl, g_wk_lo);
    cudaGetSymbolAddress((void**)&wvh, g_wv_hi); cudaGetSymbolAddress((void**)&wvl, g_wv_lo);
    cudaGetSymbolAddress((void**)&woh, g_wo_hi); cudaGetSymbolAddress((void**)&wol, g_wo_lo);
    cudaGetSymbolAddress((void**)&f1h, g_f1_hi); cudaGetSymbolAddress((void**)&f1l, g_f1_lo);
    cudaGetSymbolAddress((void**)&f2h, g_f2_hi); cudaGetSymbolAddress((void**)&f2l, g_f2_lo);
    cudaGetSymbolAddress((void**)&pqh, g_pqw_hi); cudaGetSymbolAddress((void**)&pql, g_pqw_lo);
    cudaGetSymbolAddress((void**)&pkh, g_pkw_hi); cudaGetSymbolAddress((void**)&pkl, g_pkw_lo);

    cudaFuncSetAttribute(attn3_kernel, cudaFuncAttributeMaxDynamicSharedMemorySize, ATTN_SMEM);
    cudaFuncSetAttribute(pair_tc2_kernel, cudaFuncAttributeMaxDynamicSharedMemorySize, PAIR_SMEM);

    bucket_kernel<<<(L * L + 255) / 256, 256>>>(bucket);
    embed_kernel<<<L, D>>>(seq, tok_emb, x);
    relbias_kernel<<<(H * 1536 + 255) / 256, 256>>>(rp_emb, relbias);
    presplit2_kernel<<<dim3(256, NLAYER), 256>>>(ffn_w1, f1h, f1l, D, DFF);   // #4 profiled
    presplit2_kernel<<<dim3(64, NLAYER), 256>>>(wq, wqh, wql, D, D);
    presplit2_kernel<<<dim3(64, NLAYER), 256>>>(wk, wkh, wkl, D, D);
    presplit2_kernel<<<dim3(64, NLAYER), 256>>>(wv, wvh, wvl, D, D);
    presplit2_kernel<<<dim3(64, NLAYER), 256>>>(wo, woh, wol, D, D);
    presplit2_kernel<<<dim3(256, NLAYER), 256>>>(ffn_w2, f2h, f2l, DFF, D);
    presplit2_kernel<<<dim3(64, 1), 256>>>(pair_q_w, pqh, pql, D, D);
    presplit2_kernel<<<dim3(64, 1), 256>>>(pair_k_w, pkh, pkl, D, D);
    e1_kernel<<<NB, D>>>(pair_rp, cls_w1, cls_b1, E1);
    w1t_kernel<<<D * D / 256, 256>>>(cls_w1, W1t);

    dim3 gqkv(D / 64, L / 64, 3);
    dim3 g256(D / 64, L / 64);
    dim3 gff1(DFF / 64, L / 64);
    dim3 gpqpk(D / 64, L / 64, 2);

    for (int layer = 0; layer < NLAYER; layer++) {
        ln_kernel<<<L, D>>>(x, ln1_s + layer * D, ln1_b + layer * D, h);
        hgemm_qkv_kernel<<<gqkv, 256>>>(h, layer, q, k, v);
        attn3_kernel<<<dim3(L / QT, H), 256, ATTN_SMEM>>>(q, k, v, relbias, attn);
        hgemm_kernel<4><<<g256, 256>>>(attn, woh + (size_t)layer * D * D,
                                       wol + (size_t)layer * D * D, x,
                                       nullptr, x, L, D, D);
        ln_kernel<<<L, D>>>(x, ln2_s + layer * D, ln2_b + layer * D, h);
        hgemm_kernel<2><<<gff1, 256>>>(h, f1h + (size_t)layer * D * DFF,
                                       f1l + (size_t)layer * D * DFF, ff,
                                       ffn_b1 + layer * DFF, nullptr, L, DFF, D);
        hgemm_kernel<3><<<g256, 256>>>(ff, f2h + (size_t)layer * DFF * D,
                                       f2l + (size_t)layer * DFF * D, x,
                                       ffn_b2 + layer * D, x, L, D, DFF);
    }

    ln_kernel<<<L, D>>>(x, lnf_s, lnf_b, h);
    hgemm_pqpk_kernel<<<gpqpk, 256>>>(h, pair_q_b, pair_k_b, pq, pk);

    pair_tc2_kernel<<<dim3(L / TJ, L / TI), 1024, PAIR_SMEM>>>(
        pq, pk, W1t, E1, cls_w2, cls_b2, bucket, out);
}

// round 14
// speedup vs baseline: 1.6108x; 1.0196x over previous
#include <cuda_runtime.h>
#include <cuda_bf16.h>
#include <math.h>

#define L 768
#define D 256
#define H 8
#define DK 32
#define DFF 1024
#define NB 64
#define NLAYER 8

// ---------------- device scratch ----------------
__device__ float g_x[L * D];
__device__ float g_h[L * D];
__device__ float g_q[L * D];
__device__ float g_k[L * D];
__device__ float g_v[L * D];
__device__ float g_attn[L * D];
__device__ float g_ff[L * DFF];
__device__ float g_pq[L * D];
__device__ float g_pk[L * D];
__device__ float g_E1[NB * D];
__device__ unsigned g_W1t[D * D];
__device__ float g_relbias[H * 1536];

__device__ __nv_bfloat16 g_wq_hi[NLAYER * D * D], g_wq_lo[NLAYER * D * D];
__device__ __nv_bfloat16 g_wk_hi[NLAYER * D * D], g_wk_lo[NLAYER * D * D];
__device__ __nv_bfloat16 g_wv_hi[NLAYER * D * D], g_wv_lo[NLAYER * D * D];
__device__ __nv_bfloat16 g_wo_hi[NLAYER * D * D], g_wo_lo[NLAYER * D * D];
__device__ __nv_bfloat16 g_f1_hi[NLAYER * D * DFF], g_f1_lo[NLAYER * D * DFF];
__device__ __nv_bfloat16 g_f2_hi[NLAYER * DFF * D], g_f2_lo[NLAYER * DFF * D];
__device__ __nv_bfloat16 g_pqw_hi[D * D], g_pqw_lo[D * D];
__device__ __nv_bfloat16 g_pkw_hi[D * D], g_pkw_lo[D * D];

// ---------------- helpers ----------------
__device__ __forceinline__ unsigned smem_u32(const void* p) {
    unsigned a;
    asm("{ .reg .u64 t; cvta.to.shared.u64 t, %1; cvt.u32.u64 %0, t; }" : "=r"(a) : "l"(p));
    return a;
}
__device__ __forceinline__ void cp_async16(unsigned saddr, const void* gptr) {
    asm volatile("cp.async.cg.shared.global [%0], [%1], 16;" :: "r"(saddr), "l"(gptr));
}
#define CP_COMMIT() asm volatile("cp.async.commit_group;")
#define CP_WAIT0()  asm volatile("cp.async.wait_group 0;")

// bucket as pure ALU/MUFU function of rel = i - j
__device__ __forceinline__ int bucket_of(int rel) {
    int ret = (rel < 0) ? 32 : 0;
    int arp = abs(rel);
    int val;
    if (arp < 16) {
        val = arp;
    } else {
        float t = logf((float)arp / 16.0f) / 2.7725887f * 16.0f;
        int vil = 16 + (int)t;
        val = vil < 31 ? vil : 31;
    }
    return ret + val;
}

__global__ void relbias_kernel(const float* __restrict__ rp_emb,
                               float* __restrict__ relbias) {
    int idx = blockIdx.x * 256 + threadIdx.x;
    if (idx >= H * 1536) return;
    int h = idx / 1536, r = idx % 1536;
    relbias[idx] = rp_emb[bucket_of(r - 768) * H + h];
}

// ---------------- embedding ----------------
__global__ void embed_kernel(const int* __restrict__ seq,
                             const float* __restrict__ tok_emb,
                             float* __restrict__ x) {
    int l = blockIdx.x;
    int d = threadIdx.x;
    x[l * D + d] = tok_emb[seq[l] * D + d];
}

// ---------------- layernorm ----------------
__global__ void ln_kernel(const float* __restrict__ x,
                          const float* __restrict__ s,
                          const float* __restrict__ b,
                          float* __restrict__ out) {
    int row = blockIdx.x;
    int tid = threadIdx.x;
    float val = x[row * D + tid];
    float s1 = val, s2 = val * val;
#pragma unroll
    for (int o = 16; o > 0; o >>= 1) {
        s1 += __shfl_xor_sync(0xffffffffu, s1, o);
        s2 += __shfl_xor_sync(0xffffffffu, s2, o);
    }
    __shared__ float r1[8], r2[8];
    if ((tid & 31) == 0) { r1[tid >> 5] = s1; r2[tid >> 5] = s2; }
    __syncthreads();
    float t1 = 0.f, t2 = 0.f;
#pragma unroll
    for (int w = 0; w < 8; w++) { t1 += r1[w]; t2 += r2[w]; }
    float m = t1 * (1.0f / D);
    float var = t2 * (1.0f / D) - m * m;
    out[row * D + tid] = (val - m) * rsqrtf(var + 1e-5f) * s[tid] + b[tid];
}

// ---------------- presplit v2: coalesced smem-tile transpose ----------------
__global__ void presplit2_kernel(const float* __restrict__ W,
                                 __nv_bfloat16* __restrict__ hiT,
                                 __nv_bfloat16* __restrict__ loT,
                                 int K, int N) {
    __shared__ float tile[32][33];
    const int tiles_n = N >> 5;
    const int tk = blockIdx.x / tiles_n, tn = blockIdx.x % tiles_n;
    const int l = blockIdx.y;
    const float* Wl = W + (size_t)l * K * N;
    __nv_bfloat16* hl = hiT + (size_t)l * K * N;
    __nv_bfloat16* ll = loT + (size_t)l * K * N;
    const int r = threadIdx.x >> 5, c = threadIdx.x & 31;
#pragma unroll
    for (int p = 0; p < 4; p++)
        tile[r + p * 8][c] = Wl[(size_t)(tk * 32 + r + p * 8) * N + tn * 32 + c];
    __syncthreads();
#pragma unroll
    for (int p = 0; p < 4; p++) {
        int n = tn * 32 + r + p * 8;
        int kk = tk * 32 + c;
        float a = tile[c][r + p * 8];
        __nv_bfloat16 hh = __float2bfloat16(a);
        hl[(size_t)n * K + kk] = hh;
        ll[(size_t)n * K + kk] = __float2bfloat16(a - __bfloat162float(hh));
    }
}

// ---------------- bf16-split HMMA GEMM, double-buffered + cp.async ---------
__device__ __forceinline__ float gelu_exact(float x) {
    return 0.5f * x * (1.0f + erff(x * 0.70710678118654752f));
}

__device__ __forceinline__ void mma_bf16(float* c, const unsigned* a, unsigned b0, unsigned b1) {
    asm volatile(
        "mma.sync.aligned.m16n8k16.row.col.f32.bf16.bf16.f32 "
        "{%0,%1,%2,%3}, {%4,%5,%6,%7}, {%8,%9}, {%0,%1,%2,%3};"
        : "+f"(c[0]), "+f"(c[1]), "+f"(c[2]), "+f"(c[3])
        : "r"(a[0]), "r"(a[1]), "r"(a[2]), "r"(a[3]), "r"(b0), "r"(b1));
}

__device__ __forceinline__ unsigned packsplit(float a, float b, unsigned& lo) {
    __nv_bfloat16 ha = __float2bfloat16(a), hb = __float2bfloat16(b);
    __nv_bfloat16 la = __float2bfloat16(a - __bfloat162float(ha));
    __nv_bfloat16 lb = __float2bfloat16(b - __bfloat162float(hb));
    lo = (unsigned)__bfloat16_as_ushort(la) | ((unsigned)__bfloat16_as_ushort(lb) << 16);
    return (unsigned)__bfloat16_as_ushort(ha) | ((unsigned)__bfloat16_as_ushort(hb) << 16);
}

#define HPAD 20

// BM in {64, 32}. 256 threads, 8 warps; wm in {0,1}, MI = BM/32 m-tiles per warp.
template <int EPI, int BM>
__device__ __forceinline__ void hgemm_body(
    const float* __restrict__ A, const __nv_bfloat16* __restrict__ BhiT,
    const __nv_bfloat16* __restrict__ BloT, float* __restrict__ C,
    const float* __restrict__ bias, const float* __restrict__ res,
    int M, int N, int K, int bx, int by)
{
    constexpr int MI = BM / 32;
    __shared__ unsigned sAhi[2][BM * HPAD], sAlo[2][BM * HPAD];
    __shared__ unsigned sBhi[2][64 * HPAD], sBlo[2][64 * HPAD];
    const int tid = threadIdx.x;
    const int lane = tid & 31, warp = tid >> 5;
    const int gid = lane >> 2, tig = lane & 3;
    const int wm = warp >> 2, wn = warp & 3;
    const int row0 = by * BM, col0 = bx * 64;

    float acc[MI][2][4];
#pragma unroll
    for (int mi = 0; mi < MI; mi++)
#pragma unroll
        for (int ni = 0; ni < 2; ni++)
#pragma unroll
            for (int c = 0; c < 4; c++) acc[mi][ni][c] = 0.f;

    const int arow = tid >> 3;
    const int akq  = (tid & 7) * 4;
    const int bn   = tid >> 2;
    const int bq   = (tid & 3) * 4;

    const float* Ap0 = A + (size_t)(row0 + arow) * K + akq;
    const float* Ap1 = (BM == 64) ? A + (size_t)(row0 + arow + 32) * K + akq : Ap0;
    const __nv_bfloat16* Bph = BhiT + (size_t)(col0 + bn) * K + bq * 2;
    const __nv_bfloat16* Bpl = BloT + (size_t)(col0 + bn) * K + bq * 2;
    unsigned aBhi[2], aBlo[2];
    aBhi[0] = smem_u32(&sBhi[0][bn * HPAD + bq]);
    aBhi[1] = smem_u32(&sBhi[1][bn * HPAD + bq]);
    aBlo[0] = smem_u32(&sBlo[0][bn * HPAD + bq]);
    aBlo[1] = smem_u32(&sBlo[1][bn * HPAD + bq]);

    // ---- initial stage into buffer 0 ----
    cp_async16(aBhi[0], Bph);
    cp_async16(aBlo[0], Bpl);
    CP_COMMIT();
    {
        float4 a0 = *(const float4*)Ap0;
        unsigned lo01, lo23;
        unsigned hi01 = packsplit(a0.x, a0.y, lo01);
        unsigned hi23 = packsplit(a0.z, a0.w, lo23);
        uint2 hv; hv.x = hi01; hv.y = hi23;
        uint2 lv; lv.x = lo01; lv.y = lo23;
        *(uint2*)&sAhi[0][arow * HPAD + (akq >> 1)] = hv;
        *(uint2*)&sAlo[0][arow * HPAD + (akq >> 1)] = lv;
        if (BM == 64) {
            float4 a1 = *(const float4*)Ap1;
            hi01 = packsplit(a1.x, a1.y, lo01);
            hi23 = packsplit(a1.z, a1.w, lo23);
            hv.x = hi01; hv.y = hi23;
            lv.x = lo01; lv.y = lo23;
            *(uint2*)&sAhi[0][(arow + 32) * HPAD + (akq >> 1)] = hv;
            *(uint2*)&sAlo[0][(arow + 32) * HPAD + (akq >> 1)] = lv;
        }
    }
    CP_WAIT0();
    __syncthreads();

    const int nch = K / 32;
    for (int ch = 0; ch < nch; ch++) {
        const int cur = ch & 1, nxt = cur ^ 1;
        const bool pf = (ch + 1 < nch);
        float4 a0pre, a1pre;
        if (pf) {
            const int k0n = (ch + 1) * 32;
            cp_async16(aBhi[nxt], Bph + k0n);
            cp_async16(aBlo[nxt], Bpl + k0n);
            CP_COMMIT();
            a0pre = *(const float4*)(Ap0 + k0n);
            if (BM == 64) a1pre = *(const float4*)(Ap1 + k0n);
        }
        const unsigned* bAhi = sAhi[cur];
        const unsigned* bAlo = sAlo[cur];
        const unsigned* bBhi = sBhi[cur];
        const unsigned* bBlo = sBlo[cur];
#pragma unroll
        for (int ks = 0; ks < 2; ks++) {
            const int kb = ks * 8;
            unsigned ahi[MI][4], alo[MI][4];
#pragma unroll
            for (int mi = 0; mi < MI; mi++) {
                int R = wm * (BM / 2) + mi * 16;
                ahi[mi][0] = bAhi[(R + gid) * HPAD + kb + tig];
                ahi[mi][1] = bAhi[(R + gid + 8) * HPAD + kb + tig];
                ahi[mi][2] = bAhi[(R + gid) * HPAD + kb + tig + 4];
                ahi[mi][3] = bAhi[(R + gid + 8) * HPAD + kb + tig + 4];
                alo[mi][0] = bAlo[(R + gid) * HPAD + kb + tig];
                alo[mi][1] = bAlo[(R + gid + 8) * HPAD + kb + tig];
                alo[mi][2] = bAlo[(R + gid) * HPAD + kb + tig + 4];
                alo[mi][3] = bAlo[(R + gid + 8) * HPAD + kb + tig + 4];
            }
#pragma unroll
            for (int ni = 0; ni < 2; ni++) {
                int nc = wn * 16 + ni * 8;
                unsigned bh0 = bBhi[(nc + gid) * HPAD + kb + tig];
                unsigned bh1 = bBhi[(nc + gid) * HPAD + kb + tig + 4];
                unsigned bl0 = bBlo[(nc + gid) * HPAD + kb + tig];
                unsigned bl1 = bBlo[(nc + gid) * HPAD + kb + tig + 4];
#pragma unroll
                for (int mi = 0; mi < MI; mi++) {
                    mma_bf16(acc[mi][ni], ahi[mi], bh0, bh1);
                    mma_bf16(acc[mi][ni], ahi[mi], bl0, bl1);
                    mma_bf16(acc[mi][ni], alo[mi], bh0, bh1);
                }
            }
        }
        if (pf) {
            unsigned lo01, lo23;
            unsigned hi01 = packsplit(a0pre.x, a0pre.y, lo01);
            unsigned hi23 = packsplit(a0pre.z, a0pre.w, lo23);
            uint2 hv; hv.x = hi01; hv.y = hi23;
            uint2 lv; lv.x = lo01; lv.y = lo23;
            *(uint2*)&sAhi[nxt][arow * HPAD + (akq >> 1)] = hv;
            *(uint2*)&sAlo[nxt][arow * HPAD + (akq >> 1)] = lv;
            if (BM == 64) {
                hi01 = packsplit(a1pre.x, a1pre.y, lo01);
                hi23 = packsplit(a1pre.z, a1pre.w, lo23);
                hv.x = hi01; hv.y = hi23;
                lv.x = lo01; lv.y = lo23;
                *(uint2*)&sAhi[nxt][(arow + 32) * HPAD + (akq >> 1)] = hv;
                *(uint2*)&sAlo[nxt][(arow + 32) * HPAD + (akq >> 1)] = lv;
            }
            CP_WAIT0();
        }
        __syncthreads();
    }

#pragma unroll
    for (int mi = 0; mi < MI; mi++) {
#pragma unroll
        for (int ni = 0; ni < 2; ni++) {
            int m0 = row0 + wm * (BM / 2) + mi * 16 + gid;
            int n = col0 + wn * 16 + ni * 8 + tig * 2;
            float v0 = acc[mi][ni][0], v1 = acc[mi][ni][1];
            float v2 = acc[mi][ni][2], v3 = acc[mi][ni][3];
            if (EPI == 1 || EPI == 2 || EPI == 3) {
                float2 bb = *(const float2*)&bias[n];
                v0 += bb.x; v1 += bb.y; v2 += bb.x; v3 += bb.y;
            }
            if (EPI == 2) {
                v0 = gelu_exact(v0); v1 = gelu_exact(v1);
                v2 = gelu_exact(v2); v3 = gelu_exact(v3);
            }
            if (EPI == 3 || EPI == 4) {
                float2 r0 = *(const float2*)&res[(size_t)m0 * N + n];
                float2 r1 = *(const float2*)&res[(size_t)(m0 + 8) * N + n];
                v0 += r0.x; v1 += r0.y; v2 += r1.x; v3 += r1.y;
            }
            float2 o0; o0.x = v0; o0.y = v1;
            float2 o1; o1.x = v2; o1.y = v3;
            *(float2*)&C[(size_t)m0 * N + n] = o0;
            *(float2*)&C[(size_t)(m0 + 8) * N + n] = o1;
        }
    }
}

template <int EPI, int BM>
__global__ void __launch_bounds__(256, 3)
hgemm_kernel(const float* __restrict__ A, const __nv_bfloat16* __restrict__ BhiT,
             const __nv_bfloat16* __restrict__ BloT, float* __restrict__ C,
             const float* __restrict__ bias, const float* __restrict__ res,
             int M, int N, int K) {
    hgemm_body<EPI, BM>(A, BhiT, BloT, C, bias, res, M, N, K, blockIdx.x, blockIdx.y);
}

__global__ void __launch_bounds__(256, 3)
hgemm_qkv_kernel(const float* __restrict__ A, int layer,
                 float* __restrict__ q, float* __restrict__ k, float* __restrict__ v) {
    const size_t off = (size_t)layer * D * D;
    const __nv_bfloat16 *bh, *bl;
    float* C;
    if (blockIdx.z == 0)      { bh = g_wq_hi + off; bl = g_wq_lo + off; C = q; }
    else if (blockIdx.z == 1) { bh = g_wk_hi + off; bl = g_wk_lo + off; C = k; }
    else                      { bh = g_wv_hi + off; bl = g_wv_lo + off; C = v; }
    hgemm_body<0, 64>(A, bh, bl, C, nullptr, nullptr, L, D, D, blockIdx.x, blockIdx.y);
}

__global__ void __launch_bounds__(256, 3)
hgemm_pqpk_kernel(const float* __restrict__ A,
                  const float* __restrict__ bq, const float* __restrict__ bk,
                  float* __restrict__ pq, float* __restrict__ pk) {
    const __nv_bfloat16 *bh, *bl;
    const float* bias;
    float* C;
    if (blockIdx.z == 0) { bh = g_pqw_hi; bl = g_pqw_lo; bias = bq; C = pq; }
    else                 { bh = g_pkw_hi; bl = g_pkw_lo; bias = bk; C = pk; }
    hgemm_body<1, 32>(A, bh, bl, C, bias, nullptr, L, D, D, blockIdx.x, blockIdx.y);
}

// ---------------- attention ----------------
#define QT 16
#define ATTN_SMEM ((QT * DK + 784 + QT * L + QT) * 4)
__global__ void __launch_bounds__(256, 3)
attn3_kernel(const float* __restrict__ q, const float* __restrict__ k,
             const float* __restrict__ v, const float* __restrict__ relbias,
             float* __restrict__ out) {
    extern __shared__ unsigned char smraw[];
    float* sq = (float*)smraw;
    float* sbias = sq + QT * DK;
    float* sp = sbias + 784;
    float* sinv = sp + QT * L;
    const int i0 = blockIdx.x * QT;
    const int h = blockIdx.y;
    const int tid = threadIdx.x;
    const float invscale = 0.17677669529663687f;

    for (int t = tid; t < QT * DK; t += 256)
        sq[t] = q[(i0 + (t >> 5)) * D + h * DK + (t & 31)];
    for (int t = tid; t < 783; t += 256)
        sbias[t] = relbias[h * 1536 + i0 + 1 + t];
    __syncthreads();

#pragma unroll
    for (int it = 0; it < 3; it++) {
        int j = tid + it * 256;
        float4 kv[8];
        const float4* kr = (const float4*)(k + (size_t)j * D + h * DK);
#pragma unroll
        for (int t = 0; t < 8; t++) kv[t] = kr[t];
        float dot[QT];
#pragma unroll
        for (int qi = 0; qi < QT; qi++) dot[qi] = 0.f;
#pragma unroll
        for (int t = 0; t < 8; t++) {
#pragma unroll
            for (int qi = 0; qi < QT; qi++) {
                float4 qv = *(const float4*)(sq + qi * DK + t * 4);
                dot[qi] += qv.x * kv[t].x + qv.y * kv[t].y + qv.z * kv[t].z + qv.w * kv[t].w;
            }
        }
#pragma unroll
        for (int qi = 0; qi < QT; qi++)
            sp[qi * L + j] = dot[qi] * invscale + sbias[qi - j + 767];
    }
    __syncthreads();

    const int warp = tid >> 5, lane = tid & 31;
#pragma unroll
    for (int qq = 0; qq < 2; qq++) {
        int qi = warp * 2 + qq;
        float m = -1e30f;
        for (int j = lane; j < L; j += 32) m = fmaxf(m, sp[qi * L + j]);
#pragma unroll
        for (int o = 16; o > 0; o >>= 1) m = fmaxf(m, __shfl_xor_sync(0xffffffffu, m, o));
        float s = 0.f;
        for (int j = lane; j < L; j += 32) {
            float e = expf(sp[qi * L + j] - m);
            sp[qi * L + j] = e;
            s += e;
        }
#pragma unroll
        for (int o = 16; o > 0; o >>= 1) s += __shfl_xor_sync(0xffffffffu, s, o);
        if (lane == 0) sinv[qi] = 1.0f / s;
    }
    __syncthreads();

    {
        const int qiA = warp * 2, qiB = qiA + 1;
        const int jsub = lane >> 3, dq = lane & 7;
        float4 a0 = make_float4(0, 0, 0, 0), a1 = make_float4(0, 0, 0, 0);
        const float4* vb = (const float4*)(v + h * DK + dq * 4);
        const float* spA = sp + qiA * L;
        const float* spB = sp + qiB * L;
#pragma unroll 3
        for (int j = 0; j < L; j += 16) {
            float4 vv[4];
            float sA[4], sB[4];
#pragma unroll
            for (int t = 0; t < 4; t++) {
                int jj = j + t * 4 + jsub;
                vv[t] = vb[(size_t)jj * (D / 4)];
                sA[t] = spA[jj];
                sB[t] = spB[jj];
            }
#pragma unroll
            for (int t = 0; t < 4; t++) {
                a0.x += sA[t] * vv[t].x; a0.y += sA[t] * vv[t].y;
                a0.z += sA[t] * vv[t].z; a0.w += sA[t] * vv[t].w;
                a1.x += sB[t] * vv[t].x; a1.y += sB[t] * vv[t].y;
                a1.z += sB[t] * vv[t].z; a1.w += sB[t] * vv[t].w;
            }
        }
#pragma unroll
        for (int o = 8; o <= 16; o <<= 1) {
            a0.x += __shfl_xor_sync(0xffffffffu, a0.x, o);
            a0.y += __shfl_xor_sync(0xffffffffu, a0.y, o);
            a0.z += __shfl_xor_sync(0xffffffffu, a0.z, o);
            a0.w += __shfl_xor_sync(0xffffffffu, a0.w, o);
            a1.x += __shfl_xor_sync(0xffffffffu, a1.x, o);
            a1.y += __shfl_xor_sync(0xffffffffu, a1.y, o);
            a1.z += __shfl_xor_sync(0xffffffffu, a1.z, o);
            a1.w += __shfl_xor_sync(0xffffffffu, a1.w, o);
        }
        if (jsub == 0) {
            float iA = sinv[qiA], iB = sinv[qiB];
            float4 oA = make_float4(a0.x * iA, a0.y * iA, a0.z * iA, a0.w * iA);
            float4 oB = make_float4(a1.x * iB, a1.y * iB, a1.z * iB, a1.w * iB);
            *(float4*)(out + (size_t)(i0 + qiA) * D + h * DK + dq * 4) = oA;
            *(float4*)(out + (size_t)(i0 + qiB) * D + h * DK + dq * 4) = oB;
        }
    }
}

// ---------------- E1 ----------------
__global__ void e1_kernel(const float* __restrict__ rp, const float* __restrict__ W1,
                          const float* __restrict__ b1, float* __restrict__ E1) {
    int b = blockIdx.x;
    int d = threadIdx.x;
    float s = b1[d];
    for (int c = 0; c < D; c++) s += rp[b * D + c] * W1[c * D + d];
    E1[b * D + d] = s;
}

// ---------------- tf32 helpers (pair head) ----------------
__device__ __forceinline__ unsigned f2tf32(float x) {
    unsigned r;
    asm("cvt.rna.tf32.f32 %0, %1;" : "=r"(r) : "f"(x));
    return r;
}

__device__ __forceinline__ void mma_tf32(float* c, const unsigned* a, unsigned b0, unsigned b1) {
    asm volatile(
        "mma.sync.aligned.m16n8k8.row.col.f32.tf32.tf32.f32 "
        "{%0,%1,%2,%3}, {%4,%5,%6,%7}, {%8,%9}, {%0,%1,%2,%3};"
        : "+f"(c[0]), "+f"(c[1]), "+f"(c[2]), "+f"(c[3])
        : "r"(a[0]), "r"(a[1]), "r"(a[2]), "r"(a[3]), "r"(b0), "r"(b1));
}

__global__ void w1t_kernel(const float* __restrict__ W1, unsigned* __restrict__ W1t) {
    int t = blockIdx.x * 256 + threadIdx.x;
    W1t[t] = f2tf32(W1[t]);
}

// ---------------- pair head: tf32 HMMA, 1024 threads ----------------
#define TI 4
#define TJ 32
#define PAD_A 36
#define PAD_B 264
#define PAD_E 260
#define AS_STRIDE (128 * PAD_A)
#define WS_STRIDE (32 * PAD_B)
#define PAIR_SMEM ((1024 + 512 + 2048 + NB * PAD_E + 2 * AS_STRIDE + 2 * WS_STRIDE) * 4)

__global__ void __launch_bounds__(1024, 1)
pair_tc2_kernel(const float* __restrict__ pq, const float* __restrict__ pk,
                const unsigned* __restrict__ W1t, const float* __restrict__ E1,
                const float* __restrict__ W2, const float* __restrict__ b2,
                float* __restrict__ out) {
    extern __shared__ unsigned char smraw[];
    float*    qs  = (float*)smraw;
    float*    w2s = qs + 1024;
    float*    red = w2s + 512;
    float*    E1s = red + 2048;
    unsigned* As  = (unsigned*)(E1s + NB * PAD_E);
    unsigned* Ws  = As + 2 * AS_STRIDE;

    const int i0 = blockIdx.y * TI;
    const int j0 = blockIdx.x * TJ;
    const int tid = threadIdx.x;
    const int lane = tid & 31, warp = tid >> 5;
    const int gid = lane >> 2, tig = lane & 3;
    const int wm = warp >> 3;
    const int wn = warp & 7;

    if (tid < 256) ((float4*)qs)[tid] = ((const float4*)(pq + (size_t)i0 * D))[tid];
    if (tid < 512) w2s[tid] = W2[tid];
#pragma unroll
    for (int t = 0; t < 4; t++) {
        int idx = tid + t * 1024;
        int b = idx >> 6, d4 = (idx & 63) << 2;
        *(float4*)&E1s[b * PAD_E + d4] = *(const float4*)&E1[b * D + d4];
    }

    float acc[2][4][4] = {};

    const int pfill = tid >> 3;
    const int ccb = (tid & 7) * 4;
    const int ilf = pfill >> 5, jlf = pfill & 31;
    const float* pkrow = pk + (size_t)(j0 + jlf) * D;
    const float* qsrow = qs + ilf * D;
    const int wr0 = tid >> 6, wc0 = (tid & 63) << 2;

#pragma unroll
    for (int t = 0; t < 2; t++) {
        int row = wr0 + t * 16;
        *(uint4*)(Ws + row * PAD_B + wc0) = *(const uint4*)(W1t + (size_t)row * D + wc0);
    }
    __syncthreads();
    {
        float4 kv = *(const float4*)(pkrow + ccb);
        float4 qv = *(const float4*)(qsrow + ccb);
        uint4 o;
        o.x = f2tf32(kv.x * qv.x);
        o.y = f2tf32(kv.y * qv.y);
        o.z = f2tf32(kv.z * qv.z);
        o.w = f2tf32(kv.w * qv.w);
        *(uint4*)(As + pfill * PAD_A + ccb) = o;
    }
    __syncthreads();

    for (int ch = 0; ch < 8; ch++) {
        const int cur = ch & 1;
        const int k0n = (ch + 1) * 32;
        const unsigned* Ab = As + cur * AS_STRIDE;
        const unsigned* Wb = Ws + cur * WS_STRIDE;
#pragma unroll
        for (int kf = 0; kf < 4; kf++) {
            unsigned a[2][4];
#pragma unroll
            for (int mi = 0; mi < 2; mi++) {
                int R = wm * 32 + mi * 16;
                a[mi][0] = Ab[(R + gid) * PAD_A + kf * 8 + tig];
                a[mi][1] = Ab[(R + gid + 8) * PAD_A + kf * 8 + tig];
                a[mi][2] = Ab[(R + gid) * PAD_A + kf * 8 + tig + 4];
                a[mi][3] = Ab[(R + gid + 8) * PAD_A + kf * 8 + tig + 4];
            }
#pragma unroll
            for (int ni = 0; ni < 4; ni++) {
                unsigned b0 = Wb[(kf * 8 + tig) * PAD_B + wn * 32 + ni * 8 + gid];
                unsigned b1 = Wb[(kf * 8 + tig + 4) * PAD_B + wn * 32 + ni * 8 + gid];
                mma_tf32(acc[0][ni], a[0], b0, b1);
                mma_tf32(acc[1][ni], a[1], b0, b1);
            }
        }
        if (ch < 7) {
#pragma unroll
            for (int t = 0; t < 2; t++) {
                int row = wr0 + t * 16;
                *(uint4*)(Ws + (cur ^ 1) * WS_STRIDE + row * PAD_B + wc0) =
                    *(const uint4*)(W1t + (size_t)(k0n + row) * D + wc0);
            }
            float4 kv = *(const float4*)(pkrow + k0n + ccb);
            float4 qv = *(const float4*)(qsrow + k0n + ccb);
            uint4 o;
            o.x = f2tf32(kv.x * qv.x);
            o.y = f2tf32(kv.y * qv.y);
            o.z = f2tf32(kv.z * qv.z);
            o.w = f2tf32(kv.w * qv.w);
            *(uint4*)(As + (cur ^ 1) * AS_STRIDE + pfill * PAD_A + ccb) = o;
        }
        __syncthreads();
    }

    const float2* w2f = (const float2*)w2s;
#pragma unroll
    for (int mi = 0; mi < 2; mi++) {
#pragma unroll
        for (int half = 0; half < 2; half++) {
            int pl = wm * 32 + mi * 16 + gid + half * 8;
            int il = pl >> 5, jl = pl & 31;
            // inline bucket from rel = (i0+il) - (j0+jl)
            const float* e1row = E1s + (size_t)bucket_of((i0 + il) - (j0 + jl)) * PAD_E;
            float p0 = 0.f, p1 = 0.f;
#pragma unroll
            for (int ni = 0; ni < 4; ni++) {
#pragma unroll
                for (int col = 0; col < 2; col++) {
                    int d = wn * 32 + ni * 8 + tig * 2 + col;
                    float hv = fmaxf(acc[mi][ni][half * 2 + col] + e1row[d], 0.f);
                    float2 w2v = w2f[d];
                    p0 += hv * w2v.x;
                    p1 += hv * w2v.y;
                }
            }
            p0 += __shfl_xor_sync(0xffffffffu, p0, 1);
            p0 += __shfl_xor_sync(0xffffffffu, p0, 2);
            p1 += __shfl_xor_sync(0xffffffffu, p1, 1);
            p1 += __shfl_xor_sync(0xffffffffu, p1, 2);
            if (tig == 0) {
                red[(wn * 128 + pl) * 2]     = p0;
                red[(wn * 128 + pl) * 2 + 1] = p1;
            }
        }
    }
    __syncthreads();
    if (tid < 256) {
        int pl = tid >> 1, comp = tid & 1;
        int il = pl >> 5, jl = pl & 31;
        float s = 0.f;
#pragma unroll
        for (int g = 0; g < 8; g++) s += red[(g * 128 + pl) * 2 + comp];
        out[((long)(i0 + il) * L + (j0 + jl)) * 2 + comp] = s + b2[comp];
    }
}

// ---------------- host launch ----------------
extern "C" void kernel_launch(void* const* d_in, const int* in_sizes, int n_in,
                              void* d_out, int out_size) {
    const int*   seq      = (const int*)d_in[0];
    const float* tok_emb  = (const float*)d_in[1];
    const float* rp_emb   = (const float*)d_in[2];
    const float* wq       = (const float*)d_in[3];
    const float* wk       = (const float*)d_in[4];
    const float* wv       = (const float*)d_in[5];
    const float* wo       = (const float*)d_in[6];
    const float* ln1_s    = (const float*)d_in[7];
    const float* ln1_b    = (const float*)d_in[8];
    const float* ln2_s    = (const float*)d_in[9];
    const float* ln2_b    = (const float*)d_in[10];
    const float* ffn_w1   = (const float*)d_in[11];
    const float* ffn_b1   = (const float*)d_in[12];
    const float* ffn_w2   = (const float*)d_in[13];
    const float* ffn_b2   = (const float*)d_in[14];
    const float* lnf_s    = (const float*)d_in[15];
    const float* lnf_b    = (const float*)d_in[16];
    const float* pair_q_w = (const float*)d_in[17];
    const float* pair_q_b = (const float*)d_in[18];
    const float* pair_k_w = (const float*)d_in[19];
    const float* pair_k_b = (const float*)d_in[20];
    const float* pair_rp  = (const float*)d_in[21];
    const float* cls_w1   = (const float*)d_in[22];
    const float* cls_b1   = (const float*)d_in[23];
    const float* cls_w2   = (const float*)d_in[24];
    const float* cls_b2   = (const float*)d_in[25];
    float* out = (float*)d_out;

    float *x, *h, *q, *k, *v, *attn, *ff, *pq, *pk, *E1, *relbias;
    unsigned* W1t;
    __nv_bfloat16 *wqh, *wql, *wkh, *wkl, *wvh, *wvl, *woh, *wol;
    __nv_bfloat16 *f1h, *f1l, *f2h, *f2l, *pqh, *pql, *pkh, *pkl;
    cudaGetSymbolAddress((void**)&x, g_x);
    cudaGetSymbolAddress((void**)&h, g_h);
    cudaGetSymbolAddress((void**)&q, g_q);
    cudaGetSymbolAddress((void**)&k, g_k);
    cudaGetSymbolAddress((void**)&v, g_v);
    cudaGetSymbolAddress((void**)&attn, g_attn);
    cudaGetSymbolAddress((void**)&ff, g_ff);
    cudaGetSymbolAddress((void**)&pq, g_pq);
    cudaGetSymbolAddress((void**)&pk, g_pk);
    cudaGetSymbolAddress((void**)&E1, g_E1);
    cudaGetSymbolAddress((void**)&W1t, g_W1t);
    cudaGetSymbolAddress((void**)&relbias, g_relbias);
    cudaGetSymbolAddress((void**)&wqh, g_wq_hi); cudaGetSymbolAddress((void**)&wql, g_wq_lo);
    cudaGetSymbolAddress((void**)&wkh, g_wk_hi); cudaGetSymbolAddress((void**)&wkl, g_wk_lo);
    cudaGetSymbolAddress((void**)&wvh, g_wv_hi); cudaGetSymbolAddress((void**)&wvl, g_wv_lo);
    cudaGetSymbolAddress((void**)&woh, g_wo_hi); cudaGetSymbolAddress((void**)&wol, g_wo_lo);
    cudaGetSymbolAddress((void**)&f1h, g_f1_hi); cudaGetSymbolAddress((void**)&f1l, g_f1_lo);
    cudaGetSymbolAddress((void**)&f2h, g_f2_hi); cudaGetSymbolAddress((void**)&f2l, g_f2_lo);
    cudaGetSymbolAddress((void**)&pqh, g_pqw_hi); cudaGetSymbolAddress((void**)&pql, g_pqw_lo);
    cudaGetSymbolAddress((void**)&pkh, g_pkw_hi); cudaGetSymbolAddress((void**)&pkl, g_pkw_lo);

    cudaFuncSetAttribute(attn3_kernel, cudaFuncAttributeMaxDynamicSharedMemorySize, ATTN_SMEM);
    cudaFuncSetAttribute(pair_tc2_kernel, cudaFuncAttributeMaxDynamicSharedMemorySize, PAIR_SMEM);

    embed_kernel<<<L, D>>>(seq, tok_emb, x);
    relbias_kernel<<<(H * 1536 + 255) / 256, 256>>>(rp_emb, relbias);
    presplit2_kernel<<<dim3(256, NLAYER), 256>>>(ffn_w1, f1h, f1l, D, DFF);
    presplit2_kernel<<<dim3(64, NLAYER), 256>>>(wq, wqh, wql, D, D);
    presplit2_kernel<<<dim3(64, NLAYER), 256>>>(wk, wkh, wkl, D, D);
    presplit2_kernel<<<dim3(64, NLAYER), 256>>>(wv, wvh, wvl, D, D);
    presplit2_kernel<<<dim3(64, NLAYER), 256>>>(wo, woh, wol, D, D);
    presplit2_kernel<<<dim3(256, NLAYER), 256>>>(ffn_w2, f2h, f2l, DFF, D);
    presplit2_kernel<<<dim3(64, 1), 256>>>(pair_q_w, pqh, pql, D, D);
    presplit2_kernel<<<dim3(64, 1), 256>>>(pair_k_w, pkh, pkl, D, D);
    e1_kernel<<<NB, D>>>(pair_rp, cls_w1, cls_b1, E1);
    w1t_kernel<<<D * D / 256, 256>>>(cls_w1, W1t);

    dim3 gqkv(D / 64, L / 64, 3);        // 144 blocks, BM=64
    dim3 g32(D / 64, L / 32);            // 96 blocks, BM=32
    dim3 gff1(DFF / 64, L / 64);         // 192 blocks, BM=64
    dim3 gpqpk(D / 64, L / 32, 2);       // 192 blocks, BM=32

    for (int layer = 0; layer < NLAYER; layer++) {
        ln_kernel<<<L, D>>>(x, ln1_s + layer * D, ln1_b + layer * D, h);
        hgemm_qkv_kernel<<<gqkv, 256>>>(h, layer, q, k, v);
        attn3_kernel<<<dim3(L / QT, H), 256, ATTN_SMEM>>>(q, k, v, relbias, attn);
        hgemm_kernel<4, 32><<<g32, 256>>>(attn, woh + (size_t)layer * D * D,
                                          wol + (size_t)layer * D * D, x,
                                          nullptr, x, L, D, D);
        ln_kernel<<<L, D>>>(x, ln2_s + layer * D, ln2_b + layer * D, h);
        hgemm_kernel<2, 64><<<gff1, 256>>>(h, f1h + (size_t)layer * D * DFF,
                                           f1l + (size_t)layer * D * DFF, ff,
                                           ffn_b1 + layer * DFF, nullptr, L, DFF, D);
        hgemm_kernel<3, 32><<<g32, 256>>>(ff, f2h + (size_t)layer * DFF * D,
                                          f2l + (size_t)layer * DFF * D, x,
                                          ffn_b2 + layer * D, x, L, D, DFF);
    }

    ln_kernel<<<L, D>>>(x, lnf_s, lnf_b, h);
    hgemm_pqpk_kernel<<<gpqpk, 256>>>(h, pair_q_b, pair_k_b, pq, pk);

    pair_tc2_kernel<<<dim3(L / TJ, L / TI), 1024, PAIR_SMEM>>>(
        pq, pk, W1t, E1, cls_w2, cls_b2, out);
}

// round 15
// speedup vs baseline: 1.8597x; 1.1545x over previous
#include <cuda_runtime.h>
#include <cuda_bf16.h>
#include <math.h>

#define L 768
#define D 256
#define H 8
#define DK 32
#define DFF 1024
#define NB 64
#define NLAYER 8

// ---------------- device scratch ----------------
__device__ float g_x[L * D];
__device__ float g_h[L * D];
__device__ float g_q[L * D];
__device__ float g_k[L * D];
__device__ float g_v[L * D];
__device__ float g_attn[L * D];
__device__ float g_ff[L * DFF];
__device__ float g_pq[L * D];
__device__ float g_pk[L * D];
__device__ float g_E1[NB * D];
__device__ unsigned g_W1t[D * D];
__device__ float g_relbias[H * 1536];

__device__ __nv_bfloat16 g_wq_hi[NLAYER * D * D], g_wq_lo[NLAYER * D * D];
__device__ __nv_bfloat16 g_wk_hi[NLAYER * D * D], g_wk_lo[NLAYER * D * D];
__device__ __nv_bfloat16 g_wv_hi[NLAYER * D * D], g_wv_lo[NLAYER * D * D];
__device__ __nv_bfloat16 g_wo_hi[NLAYER * D * D], g_wo_lo[NLAYER * D * D];
__device__ __nv_bfloat16 g_f1_hi[NLAYER * D * DFF], g_f1_lo[NLAYER * D * DFF];
__device__ __nv_bfloat16 g_f2_hi[NLAYER * DFF * D], g_f2_lo[NLAYER * DFF * D];
__device__ __nv_bfloat16 g_pqw_hi[D * D], g_pqw_lo[D * D];
__device__ __nv_bfloat16 g_pkw_hi[D * D], g_pkw_lo[D * D];

// ---------------- helpers ----------------
__device__ __forceinline__ unsigned smem_u32(const void* p) {
    unsigned a;
    asm("{ .reg .u64 t; cvta.to.shared.u64 t, %1; cvt.u32.u64 %0, t; }" : "=r"(a) : "l"(p));
    return a;
}
__device__ __forceinline__ void cp_async16(unsigned saddr, const void* gptr) {
    asm volatile("cp.async.cg.shared.global [%0], [%1], 16;" :: "r"(saddr), "l"(gptr));
}
#define CP_COMMIT() asm volatile("cp.async.commit_group;")
#define CP_WAIT0()  asm volatile("cp.async.wait_group 0;")

__device__ __forceinline__ int bucket_of(int rel) {
    int ret = (rel < 0) ? 32 : 0;
    int arp = abs(rel);
    int val;
    if (arp < 16) {
        val = arp;
    } else {
        float t = logf((float)arp / 16.0f) / 2.7725887f * 16.0f;
        int vil = 16 + (int)t;
        val = vil < 31 ? vil : 31;
    }
    return ret + val;
}

__global__ void relbias_kernel(const float* __restrict__ rp_emb,
                               float* __restrict__ relbias) {
    int idx = blockIdx.x * 256 + threadIdx.x;
    if (idx >= H * 1536) return;
    int h = idx / 1536, r = idx % 1536;
    relbias[idx] = rp_emb[bucket_of(r - 768) * H + h];
}

// ---------------- embedding ----------------
__global__ void embed_kernel(const int* __restrict__ seq,
                             const float* __restrict__ tok_emb,
                             float* __restrict__ x) {
    int l = blockIdx.x;
    int d = threadIdx.x;
    x[l * D + d] = tok_emb[seq[l] * D + d];
}

// ---------------- layernorm ----------------
__global__ void ln_kernel(const float* __restrict__ x,
                          const float* __restrict__ s,
                          const float* __restrict__ b,
                          float* __restrict__ out) {
    int row = blockIdx.x;
    int tid = threadIdx.x;
    float val = x[row * D + tid];
    float s1 = val, s2 = val * val;
#pragma unroll
    for (int o = 16; o > 0; o >>= 1) {
        s1 += __shfl_xor_sync(0xffffffffu, s1, o);
        s2 += __shfl_xor_sync(0xffffffffu, s2, o);
    }
    __shared__ float r1[8], r2[8];
    if ((tid & 31) == 0) { r1[tid >> 5] = s1; r2[tid >> 5] = s2; }
    __syncthreads();
    float t1 = 0.f, t2 = 0.f;
#pragma unroll
    for (int w = 0; w < 8; w++) { t1 += r1[w]; t2 += r2[w]; }
    float m = t1 * (1.0f / D);
    float var = t2 * (1.0f / D) - m * m;
    out[row * D + tid] = (val - m) * rsqrtf(var + 1e-5f) * s[tid] + b[tid];
}

// ---------------- presplit v2: coalesced smem-tile transpose ----------------
__global__ void presplit2_kernel(const float* __restrict__ W,
                                 __nv_bfloat16* __restrict__ hiT,
                                 __nv_bfloat16* __restrict__ loT,
                                 int K, int N) {
    __shared__ float tile[32][33];
    const int tiles_n = N >> 5;
    const int tk = blockIdx.x / tiles_n, tn = blockIdx.x % tiles_n;
    const int l = blockIdx.y;
    const float* Wl = W + (size_t)l * K * N;
    __nv_bfloat16* hl = hiT + (size_t)l * K * N;
    __nv_bfloat16* ll = loT + (size_t)l * K * N;
    const int r = threadIdx.x >> 5, c = threadIdx.x & 31;
#pragma unroll
    for (int p = 0; p < 4; p++)
        tile[r + p * 8][c] = Wl[(size_t)(tk * 32 + r + p * 8) * N + tn * 32 + c];
    __syncthreads();
#pragma unroll
    for (int p = 0; p < 4; p++) {
        int n = tn * 32 + r + p * 8;
        int kk = tk * 32 + c;
        float a = tile[c][r + p * 8];
        __nv_bfloat16 hh = __float2bfloat16(a);
        hl[(size_t)n * K + kk] = hh;
        ll[(size_t)n * K + kk] = __float2bfloat16(a - __bfloat162float(hh));
    }
}

// ---------------- bf16-split HMMA GEMM, double-buffered + cp.async ---------
__device__ __forceinline__ float gelu_exact(float x) {
    return 0.5f * x * (1.0f + erff(x * 0.70710678118654752f));
}

__device__ __forceinline__ void mma_bf16(float* c, const unsigned* a, unsigned b0, unsigned b1) {
    asm volatile(
        "mma.sync.aligned.m16n8k16.row.col.f32.bf16.bf16.f32 "
        "{%0,%1,%2,%3}, {%4,%5,%6,%7}, {%8,%9}, {%0,%1,%2,%3};"
        : "+f"(c[0]), "+f"(c[1]), "+f"(c[2]), "+f"(c[3])
        : "r"(a[0]), "r"(a[1]), "r"(a[2]), "r"(a[3]), "r"(b0), "r"(b1));
}

__device__ __forceinline__ unsigned packsplit(float a, float b, unsigned& lo) {
    __nv_bfloat16 ha = __float2bfloat16(a), hb = __float2bfloat16(b);
    __nv_bfloat16 la = __float2bfloat16(a - __bfloat162float(ha));
    __nv_bfloat16 lb = __float2bfloat16(b - __bfloat162float(hb));
    lo = (unsigned)__bfloat16_as_ushort(la) | ((unsigned)__bfloat16_as_ushort(lb) << 16);
    return (unsigned)__bfloat16_as_ushort(ha) | ((unsigned)__bfloat16_as_ushort(hb) << 16);
}

#define HPAD 20

template <int EPI, int BM>
__device__ __forceinline__ void hgemm_body(
    const float* __restrict__ A, const __nv_bfloat16* __restrict__ BhiT,
    const __nv_bfloat16* __restrict__ BloT, float* __restrict__ C,
    const float* __restrict__ bias, const float* __restrict__ res,
    int M, int N, int K, int bx, int by)
{
    constexpr int MI = BM / 32;
    __shared__ unsigned sAhi[2][BM * HPAD], sAlo[2][BM * HPAD];
    __shared__ unsigned sBhi[2][64 * HPAD], sBlo[2][64 * HPAD];
    const int tid = threadIdx.x;
    const int lane = tid & 31, warp = tid >> 5;
    const int gid = lane >> 2, tig = lane & 3;
    const int wm = warp >> 2, wn = warp & 3;
    const int row0 = by * BM, col0 = bx * 64;

    float acc[MI][2][4];
#pragma unroll
    for (int mi = 0; mi < MI; mi++)
#pragma unroll
        for (int ni = 0; ni < 2; ni++)
#pragma unroll
            for (int c = 0; c < 4; c++) acc[mi][ni][c] = 0.f;

    const int arow = tid >> 3;
    const int akq  = (tid & 7) * 4;
    const int bn   = tid >> 2;
    const int bq   = (tid & 3) * 4;

    const float* Ap0 = A + (size_t)(row0 + arow) * K + akq;
    const float* Ap1 = (BM == 64) ? A + (size_t)(row0 + arow + 32) * K + akq : Ap0;
    const __nv_bfloat16* Bph = BhiT + (size_t)(col0 + bn) * K + bq * 2;
    const __nv_bfloat16* Bpl = BloT + (size_t)(col0 + bn) * K + bq * 2;
    unsigned aBhi[2], aBlo[2];
    aBhi[0] = smem_u32(&sBhi[0][bn * HPAD + bq]);
    aBhi[1] = smem_u32(&sBhi[1][bn * HPAD + bq]);
    aBlo[0] = smem_u32(&sBlo[0][bn * HPAD + bq]);
    aBlo[1] = smem_u32(&sBlo[1][bn * HPAD + bq]);

    cp_async16(aBhi[0], Bph);
    cp_async16(aBlo[0], Bpl);
    CP_COMMIT();
    {
        float4 a0 = *(const float4*)Ap0;
        unsigned lo01, lo23;
        unsigned hi01 = packsplit(a0.x, a0.y, lo01);
        unsigned hi23 = packsplit(a0.z, a0.w, lo23);
        uint2 hv; hv.x = hi01; hv.y = hi23;
        uint2 lv; lv.x = lo01; lv.y = lo23;
        *(uint2*)&sAhi[0][arow * HPAD + (akq >> 1)] = hv;
        *(uint2*)&sAlo[0][arow * HPAD + (akq >> 1)] = lv;
        if (BM == 64) {
            float4 a1 = *(const float4*)Ap1;
            hi01 = packsplit(a1.x, a1.y, lo01);
            hi23 = packsplit(a1.z, a1.w, lo23);
            hv.x = hi01; hv.y = hi23;
            lv.x = lo01; lv.y = lo23;
            *(uint2*)&sAhi[0][(arow + 32) * HPAD + (akq >> 1)] = hv;
            *(uint2*)&sAlo[0][(arow + 32) * HPAD + (akq >> 1)] = lv;
        }
    }
    CP_WAIT0();
    __syncthreads();

    const int nch = K / 32;
    for (int ch = 0; ch < nch; ch++) {
        const int cur = ch & 1, nxt = cur ^ 1;
        const bool pf = (ch + 1 < nch);
        float4 a0pre, a1pre;
        if (pf) {
            const int k0n = (ch + 1) * 32;
            cp_async16(aBhi[nxt], Bph + k0n);
            cp_async16(aBlo[nxt], Bpl + k0n);
            CP_COMMIT();
            a0pre = *(const float4*)(Ap0 + k0n);
            if (BM == 64) a1pre = *(const float4*)(Ap1 + k0n);
        }
        const unsigned* bAhi = sAhi[cur];
        const unsigned* bAlo = sAlo[cur];
        const unsigned* bBhi = sBhi[cur];
        const unsigned* bBlo = sBlo[cur];
#pragma unroll
        for (int ks = 0; ks < 2; ks++) {
            const int kb = ks * 8;
            unsigned ahi[MI][4], alo[MI][4];
#pragma unroll
            for (int mi = 0; mi < MI; mi++) {
                int R = wm * (BM / 2) + mi * 16;
                ahi[mi][0] = bAhi[(R + gid) * HPAD + kb + tig];
                ahi[mi][1] = bAhi[(R + gid + 8) * HPAD + kb + tig];
                ahi[mi][2] = bAhi[(R + gid) * HPAD + kb + tig + 4];
                ahi[mi][3] = bAhi[(R + gid + 8) * HPAD + kb + tig + 4];
                alo[mi][0] = bAlo[(R + gid) * HPAD + kb + tig];
                alo[mi][1] = bAlo[(R + gid + 8) * HPAD + kb + tig];
                alo[mi][2] = bAlo[(R + gid) * HPAD + kb + tig + 4];
                alo[mi][3] = bAlo[(R + gid + 8) * HPAD + kb + tig + 4];
            }
#pragma unroll
            for (int ni = 0; ni < 2; ni++) {
                int nc = wn * 16 + ni * 8;
                unsigned bh0 = bBhi[(nc + gid) * HPAD + kb + tig];
                unsigned bh1 = bBhi[(nc + gid) * HPAD + kb + tig + 4];
                unsigned bl0 = bBlo[(nc + gid) * HPAD + kb + tig];
                unsigned bl1 = bBlo[(nc + gid) * HPAD + kb + tig + 4];
#pragma unroll
                for (int mi = 0; mi < MI; mi++) {
                    mma_bf16(acc[mi][ni], ahi[mi], bh0, bh1);
                    mma_bf16(acc[mi][ni], ahi[mi], bl0, bl1);
                    mma_bf16(acc[mi][ni], alo[mi], bh0, bh1);
                }
            }
        }
        if (pf) {
            unsigned lo01, lo23;
            unsigned hi01 = packsplit(a0pre.x, a0pre.y, lo01);
            unsigned hi23 = packsplit(a0pre.z, a0pre.w, lo23);
            uint2 hv; hv.x = hi01; hv.y = hi23;
            uint2 lv; lv.x = lo01; lv.y = lo23;
            *(uint2*)&sAhi[nxt][arow * HPAD + (akq >> 1)] = hv;
            *(uint2*)&sAlo[nxt][arow * HPAD + (akq >> 1)] = lv;
            if (BM == 64) {
                hi01 = packsplit(a1pre.x, a1pre.y, lo01);
                hi23 = packsplit(a1pre.z, a1pre.w, lo23);
                hv.x = hi01; hv.y = hi23;
                lv.x = lo01; lv.y = lo23;
                *(uint2*)&sAhi[nxt][(arow + 32) * HPAD + (akq >> 1)] = hv;
                *(uint2*)&sAlo[nxt][(arow + 32) * HPAD + (akq >> 1)] = lv;
            }
            CP_WAIT0();
        }
        __syncthreads();
    }

#pragma unroll
    for (int mi = 0; mi < MI; mi++) {
#pragma unroll
        for (int ni = 0; ni < 2; ni++) {
            int m0 = row0 + wm * (BM / 2) + mi * 16 + gid;
            int n = col0 + wn * 16 + ni * 8 + tig * 2;
            float v0 = acc[mi][ni][0], v1 = acc[mi][ni][1];
            float v2 = acc[mi][ni][2], v3 = acc[mi][ni][3];
            if (EPI == 1 || EPI == 2 || EPI == 3) {
                float2 bb = *(const float2*)&bias[n];
                v0 += bb.x; v1 += bb.y; v2 += bb.x; v3 += bb.y;
            }
            if (EPI == 2) {
                v0 = gelu_exact(v0); v1 = gelu_exact(v1);
                v2 = gelu_exact(v2); v3 = gelu_exact(v3);
            }
            if (EPI == 3 || EPI == 4) {
                float2 r0 = *(const float2*)&res[(size_t)m0 * N + n];
                float2 r1 = *(const float2*)&res[(size_t)(m0 + 8) * N + n];
                v0 += r0.x; v1 += r0.y; v2 += r1.x; v3 += r1.y;
            }
            float2 o0; o0.x = v0; o0.y = v1;
            float2 o1; o1.x = v2; o1.y = v3;
            *(float2*)&C[(size_t)m0 * N + n] = o0;
            *(float2*)&C[(size_t)(m0 + 8) * N + n] = o1;
        }
    }
}

template <int EPI, int BM>
__global__ void __launch_bounds__(256, 3)
hgemm_kernel(const float* __restrict__ A, const __nv_bfloat16* __restrict__ BhiT,
             const __nv_bfloat16* __restrict__ BloT, float* __restrict__ C,
             const float* __restrict__ bias, const float* __restrict__ res,
             int M, int N, int K) {
    hgemm_body<EPI, BM>(A, BhiT, BloT, C, bias, res, M, N, K, blockIdx.x, blockIdx.y);
}

__global__ void __launch_bounds__(256, 3)
hgemm_qkv_kernel(const float* __restrict__ A, int layer,
                 float* __restrict__ q, float* __restrict__ k, float* __restrict__ v) {
    const size_t off = (size_t)layer * D * D;
    const __nv_bfloat16 *bh, *bl;
    float* C;
    if (blockIdx.z == 0)      { bh = g_wq_hi + off; bl = g_wq_lo + off; C = q; }
    else if (blockIdx.z == 1) { bh = g_wk_hi + off; bl = g_wk_lo + off; C = k; }
    else                      { bh = g_wv_hi + off; bl = g_wv_lo + off; C = v; }
    hgemm_body<0, 64>(A, bh, bl, C, nullptr, nullptr, L, D, D, blockIdx.x, blockIdx.y);
}

__global__ void __launch_bounds__(256, 3)
hgemm_pqpk_kernel(const float* __restrict__ A,
                  const float* __restrict__ bq, const float* __restrict__ bk,
                  float* __restrict__ pq, float* __restrict__ pk) {
    const __nv_bfloat16 *bh, *bl;
    const float* bias;
    float* C;
    if (blockIdx.z == 0) { bh = g_pqw_hi; bl = g_pqw_lo; bias = bq; C = pq; }
    else                 { bh = g_pkw_hi; bl = g_pkw_lo; bias = bk; C = pk; }
    hgemm_body<1, 32>(A, bh, bl, C, bias, nullptr, L, D, D, blockIdx.x, blockIdx.y);
}

// ---------------- attention v4: smem-tiled K/V (coalesced staging) ---------
#define QT 16
#define KTPAD 36
// floats: sq 512 + sbias 784 + sp 12288 + sinv 16 + ktile 128*36
#define ATTN_SMEM ((QT * DK + 784 + QT * L + QT + 128 * KTPAD) * 4)
__global__ void __launch_bounds__(256, 3)
attn4_kernel(const float* __restrict__ q, const float* __restrict__ k,
             const float* __restrict__ v, const float* __restrict__ relbias,
             float* __restrict__ out) {
    extern __shared__ unsigned char smraw[];
    float* sq = (float*)smraw;            // [16][32]
    float* sbias = sq + QT * DK;          // [784]
    float* sp = sbias + 784;              // [16][768]
    float* sinv = sp + QT * L;            // [16]
    float* kt = sinv + 16;                // [128][KTPAD]
    const int i0 = blockIdx.x * QT;
    const int h = blockIdx.y;
    const int tid = threadIdx.x;
    const float invscale = 0.17677669529663687f;

    for (int t = tid; t < QT * DK; t += 256)
        sq[t] = q[(i0 + (t >> 5)) * D + h * DK + (t & 31)];
    for (int t = tid; t < 783; t += 256)
        sbias[t] = relbias[h * 1536 + i0 + 1 + t];

    const int srow = tid >> 3;            // 0..31 (4 passes of 32 rows)
    const int scol = (tid & 7) * 4;       // float col
    const int jl = tid & 127;             // j within tile
    const int qb = (tid >> 7) * 8;        // 0 or 8
    __syncthreads();

    // ---- pass 1: scores, 6 tiles of 128 j ----
    for (int jt = 0; jt < 6; jt++) {
        const int j0t = jt * 128;
        if (jt) __syncthreads();          // readers of previous tile done
#pragma unroll
        for (int p = 0; p < 4; p++) {
            int row = srow + p * 32;
            float4 kv = *(const float4*)(k + (size_t)(j0t + row) * D + h * DK + scol);
            *(float4*)(kt + row * KTPAD + scol) = kv;
        }
        __syncthreads();
        float4 kv[8];
#pragma unroll
        for (int t = 0; t < 8; t++) kv[t] = *(const float4*)(kt + jl * KTPAD + t * 4);
        float dot[8];
#pragma unroll
        for (int u = 0; u < 8; u++) dot[u] = 0.f;
#pragma unroll
        for (int t = 0; t < 8; t++) {
#pragma unroll
            for (int u = 0; u < 8; u++) {
                float4 qv = *(const float4*)(sq + (qb + u) * DK + t * 4);
                dot[u] += qv.x * kv[t].x + qv.y * kv[t].y + qv.z * kv[t].z + qv.w * kv[t].w;
            }
        }
        const int j = j0t + jl;
#pragma unroll
        for (int u = 0; u < 8; u++)
            sp[(qb + u) * L + j] = dot[u] * invscale + sbias[(qb + u) - j + 767];
    }
    __syncthreads();

    // ---- softmax ----
    const int warp = tid >> 5, lane = tid & 31;
#pragma unroll
    for (int qq = 0; qq < 2; qq++) {
        int qi = warp * 2 + qq;
        float m = -1e30f;
        for (int j = lane; j < L; j += 32) m = fmaxf(m, sp[qi * L + j]);
#pragma unroll
        for (int o = 16; o > 0; o >>= 1) m = fmaxf(m, __shfl_xor_sync(0xffffffffu, m, o));
        float s = 0.f;
        for (int j = lane; j < L; j += 32) {
            float e = expf(sp[qi * L + j] - m);
            sp[qi * L + j] = e;
            s += e;
        }
#pragma unroll
        for (int o = 16; o > 0; o >>= 1) s += __shfl_xor_sync(0xffffffffu, s, o);
        if (lane == 0) sinv[qi] = 1.0f / s;
    }

    // ---- pass 2: AV, 6 tiles of 128 j (v staged into kt) ----
    const int qiA = warp * 2, qiB = qiA + 1;
    const int jsub = lane >> 3, dq = lane & 7;
    float4 a0 = make_float4(0, 0, 0, 0), a1 = make_float4(0, 0, 0, 0);
    const float* spA = sp + qiA * L;
    const float* spB = sp + qiB * L;
    for (int jt = 0; jt < 6; jt++) {
        const int j0t = jt * 128;
        __syncthreads();                  // softmax / previous-tile readers done
#pragma unroll
        for (int p = 0; p < 4; p++) {
            int row = srow + p * 32;
            float4 vv = *(const float4*)(v + (size_t)(j0t + row) * D + h * DK + scol);
            *(float4*)(kt + row * KTPAD + scol) = vv;
        }
        __syncthreads();
#pragma unroll 4
        for (int jj = 0; jj < 128; jj += 4) {
            int r = jj + jsub;
            float4 vv = *(const float4*)(kt + r * KTPAD + dq * 4);
            float sA = spA[j0t + r], sB = spB[j0t + r];
            a0.x += sA * vv.x; a0.y += sA * vv.y; a0.z += sA * vv.z; a0.w += sA * vv.w;
            a1.x += sB * vv.x; a1.y += sB * vv.y; a1.z += sB * vv.z; a1.w += sB * vv.w;
        }
    }
#pragma unroll
    for (int o = 8; o <= 16; o <<= 1) {
        a0.x += __shfl_xor_sync(0xffffffffu, a0.x, o);
        a0.y += __shfl_xor_sync(0xffffffffu, a0.y, o);
        a0.z += __shfl_xor_sync(0xffffffffu, a0.z, o);
        a0.w += __shfl_xor_sync(0xffffffffu, a0.w, o);
        a1.x += __shfl_xor_sync(0xffffffffu, a1.x, o);
        a1.y += __shfl_xor_sync(0xffffffffu, a1.y, o);
        a1.z += __shfl_xor_sync(0xffffffffu, a1.z, o);
        a1.w += __shfl_xor_sync(0xffffffffu, a1.w, o);
    }
    if (jsub == 0) {
        float iA = sinv[qiA], iB = sinv[qiB];
        float4 oA = make_float4(a0.x * iA, a0.y * iA, a0.z * iA, a0.w * iA);
        float4 oB = make_float4(a1.x * iB, a1.y * iB, a1.z * iB, a1.w * iB);
        *(float4*)(out + (size_t)(i0 + qiA) * D + h * DK + dq * 4) = oA;
        *(float4*)(out + (size_t)(i0 + qiB) * D + h * DK + dq * 4) = oB;
    }
}

// ---------------- E1 ----------------
__global__ void e1_kernel(const float* __restrict__ rp, const float* __restrict__ W1,
                          const float* __restrict__ b1, float* __restrict__ E1) {
    int b = blockIdx.x;
    int d = threadIdx.x;
    float s = b1[d];
    for (int c = 0; c < D; c++) s += rp[b * D + c] * W1[c * D + d];
    E1[b * D + d] = s;
}

// ---------------- tf32 helpers (pair head) ----------------
__device__ __forceinline__ unsigned f2tf32(float x) {
    unsigned r;
    asm("cvt.rna.tf32.f32 %0, %1;" : "=r"(r) : "f"(x));
    return r;
}

__device__ __forceinline__ void mma_tf32(float* c, const unsigned* a, unsigned b0, unsigned b1) {
    asm volatile(
        "mma.sync.aligned.m16n8k8.row.col.f32.tf32.tf32.f32 "
        "{%0,%1,%2,%3}, {%4,%5,%6,%7}, {%8,%9}, {%0,%1,%2,%3};"
        : "+f"(c[0]), "+f"(c[1]), "+f"(c[2]), "+f"(c[3])
        : "r"(a[0]), "r"(a[1]), "r"(a[2]), "r"(a[3]), "r"(b0), "r"(b1));
}

__global__ void w1t_kernel(const float* __restrict__ W1, unsigned* __restrict__ W1t) {
    int t = blockIdx.x * 256 + threadIdx.x;
    W1t[t] = f2tf32(W1[t]);
}

// ---------------- pair head: tf32 HMMA, 1024 threads ----------------
#define TI 4
#define TJ 32
#define PAD_A 36
#define PAD_B 264
#define PAD_E 260
#define AS_STRIDE (128 * PAD_A)
#define WS_STRIDE (32 * PAD_B)
#define PAIR_SMEM ((1024 + 512 + 2048 + NB * PAD_E + 2 * AS_STRIDE + 2 * WS_STRIDE) * 4)

__global__ void __launch_bounds__(1024, 1)
pair_tc2_kernel(const float* __restrict__ pq, const float* __restrict__ pk,
                const unsigned* __restrict__ W1t, const float* __restrict__ E1,
                const float* __restrict__ W2, const float* __restrict__ b2,
                float* __restrict__ out) {
    extern __shared__ unsigned char smraw[];
    float*    qs  = (float*)smraw;
    float*    w2s = qs + 1024;
    float*    red = w2s + 512;
    float*    E1s = red + 2048;
    unsigned* As  = (unsigned*)(E1s + NB * PAD_E);
    unsigned* Ws  = As + 2 * AS_STRIDE;

    const int i0 = blockIdx.y * TI;
    const int j0 = blockIdx.x * TJ;
    const int tid = threadIdx.x;
    const int lane = tid & 31, warp = tid >> 5;
    const int gid = lane >> 2, tig = lane & 3;
    const int wm = warp >> 3;
    const int wn = warp & 7;

    if (tid < 256) ((float4*)qs)[tid] = ((const float4*)(pq + (size_t)i0 * D))[tid];
    if (tid < 512) w2s[tid] = W2[tid];
#pragma unroll
    for (int t = 0; t < 4; t++) {
        int idx = tid + t * 1024;
        int b = idx >> 6, d4 = (idx & 63) << 2;
        *(float4*)&E1s[b * PAD_E + d4] = *(const float4*)&E1[b * D + d4];
    }

    float acc[2][4][4] = {};

    const int pfill = tid >> 3;
    const int ccb = (tid & 7) * 4;
    const int ilf = pfill >> 5, jlf = pfill & 31;
    const float* pkrow = pk + (size_t)(j0 + jlf) * D;
    const float* qsrow = qs + ilf * D;
    const int wr0 = tid >> 6, wc0 = (tid & 63) << 2;

#pragma unroll
    for (int t = 0; t < 2; t++) {
        int row = wr0 + t * 16;
        *(uint4*)(Ws + row * PAD_B + wc0) = *(const uint4*)(W1t + (size_t)row * D + wc0);
    }
    __syncthreads();
    {
        float4 kv = *(const float4*)(pkrow + ccb);
        float4 qv = *(const float4*)(qsrow + ccb);
        uint4 o;
        o.x = f2tf32(kv.x * qv.x);
        o.y = f2tf32(kv.y * qv.y);
        o.z = f2tf32(kv.z * qv.z);
        o.w = f2tf32(kv.w * qv.w);
        *(uint4*)(As + pfill * PAD_A + ccb) = o;
    }
    __syncthreads();

    for (int ch = 0; ch < 8; ch++) {
        const int cur = ch & 1;
        const int k0n = (ch + 1) * 32;
        const unsigned* Ab = As + cur * AS_STRIDE;
        const unsigned* Wb = Ws + cur * WS_STRIDE;
#pragma unroll
        for (int kf = 0; kf < 4; kf++) {
            unsigned a[2][4];
#pragma unroll
            for (int mi = 0; mi < 2; mi++) {
                int R = wm * 32 + mi * 16;
                a[mi][0] = Ab[(R + gid) * PAD_A + kf * 8 + tig];
                a[mi][1] = Ab[(R + gid + 8) * PAD_A + kf * 8 + tig];
                a[mi][2] = Ab[(R + gid) * PAD_A + kf * 8 + tig + 4];
                a[mi][3] = Ab[(R + gid + 8) * PAD_A + kf * 8 + tig + 4];
            }
#pragma unroll
            for (int ni = 0; ni < 4; ni++) {
                unsigned b0 = Wb[(kf * 8 + tig) * PAD_B + wn * 32 + ni * 8 + gid];
                unsigned b1 = Wb[(kf * 8 + tig + 4) * PAD_B + wn * 32 + ni * 8 + gid];
                mma_tf32(acc[0][ni], a[0], b0, b1);
                mma_tf32(acc[1][ni], a[1], b0, b1);
            }
        }
        if (ch < 7) {
#pragma unroll
            for (int t = 0; t < 2; t++) {
                int row = wr0 + t * 16;
                *(uint4*)(Ws + (cur ^ 1) * WS_STRIDE + row * PAD_B + wc0) =
                    *(const uint4*)(W1t + (size_t)(k0n + row) * D + wc0);
            }
            float4 kv = *(const float4*)(pkrow + k0n + ccb);
            float4 qv = *(const float4*)(qsrow + k0n + ccb);
            uint4 o;
            o.x = f2tf32(kv.x * qv.x);
            o.y = f2tf32(kv.y * qv.y);
            o.z = f2tf32(kv.z * qv.z);
            o.w = f2tf32(kv.w * qv.w);
            *(uint4*)(As + (cur ^ 1) * AS_STRIDE + pfill * PAD_A + ccb) = o;
        }
        __syncthreads();
    }

    const float2* w2f = (const float2*)w2s;
#pragma unroll
    for (int mi = 0; mi < 2; mi++) {
#pragma unroll
        for (int half = 0; half < 2; half++) {
            int pl = wm * 32 + mi * 16 + gid + half * 8;
            int il = pl >> 5, jl = pl & 31;
            const float* e1row = E1s + (size_t)bucket_of((i0 + il) - (j0 + jl)) * PAD_E;
            float p0 = 0.f, p1 = 0.f;
#pragma unroll
            for (int ni = 0; ni < 4; ni++) {
#pragma unroll
                for (int col = 0; col < 2; col++) {
                    int d = wn * 32 + ni * 8 + tig * 2 + col;
                    float hv = fmaxf(acc[mi][ni][half * 2 + col] + e1row[d], 0.f);
                    float2 w2v = w2f[d];
                    p0 += hv * w2v.x;
                    p1 += hv * w2v.y;
                }
            }
            p0 += __shfl_xor_sync(0xffffffffu, p0, 1);
            p0 += __shfl_xor_sync(0xffffffffu, p0, 2);
            p1 += __shfl_xor_sync(0xffffffffu, p1, 1);
            p1 += __shfl_xor_sync(0xffffffffu, p1, 2);
            if (tig == 0) {
                red[(wn * 128 + pl) * 2]     = p0;
                red[(wn * 128 + pl) * 2 + 1] = p1;
            }
        }
    }
    __syncthreads();
    if (tid < 256) {
        int pl = tid >> 1, comp = tid & 1;
        int il = pl >> 5, jl = pl & 31;
        float s = 0.f;
#pragma unroll
        for (int g = 0; g < 8; g++) s += red[(g * 128 + pl) * 2 + comp];
        out[((long)(i0 + il) * L + (j0 + jl)) * 2 + comp] = s + b2[comp];
    }
}

// ---------------- host launch ----------------
extern "C" void kernel_launch(void* const* d_in, const int* in_sizes, int n_in,
                              void* d_out, int out_size) {
    const int*   seq      = (const int*)d_in[0];
    const float* tok_emb  = (const float*)d_in[1];
    const float* rp_emb   = (const float*)d_in[2];
    const float* wq       = (const float*)d_in[3];
    const float* wk       = (const float*)d_in[4];
    const float* wv       = (const float*)d_in[5];
    const float* wo       = (const float*)d_in[6];
    const float* ln1_s    = (const float*)d_in[7];
    const float* ln1_b    = (const float*)d_in[8];
    const float* ln2_s    = (const float*)d_in[9];
    const float* ln2_b    = (const float*)d_in[10];
    const float* ffn_w1   = (const float*)d_in[11];
    const float* ffn_b1   = (const float*)d_in[12];
    const float* ffn_w2   = (const float*)d_in[13];
    const float* ffn_b2   = (const float*)d_in[14];
    const float* lnf_s    = (const float*)d_in[15];
    const float* lnf_b    = (const float*)d_in[16];
    const float* pair_q_w = (const float*)d_in[17];
    const float* pair_q_b = (const float*)d_in[18];
    const float* pair_k_w = (const float*)d_in[19];
    const float* pair_k_b = (const float*)d_in[20];
    const float* pair_rp  = (const float*)d_in[21];
    const float* cls_w1   = (const float*)d_in[22];
    const float* cls_b1   = (const float*)d_in[23];
    const float* cls_w2   = (const float*)d_in[24];
    const float* cls_b2   = (const float*)d_in[25];
    float* out = (float*)d_out;

    float *x, *h, *q, *k, *v, *attn, *ff, *pq, *pk, *E1, *relbias;
    unsigned* W1t;
    __nv_bfloat16 *wqh, *wql, *wkh, *wkl, *wvh, *wvl, *woh, *wol;
    __nv_bfloat16 *f1h, *f1l, *f2h, *f2l, *pqh, *pql, *pkh, *pkl;
    cudaGetSymbolAddress((void**)&x, g_x);
    cudaGetSymbolAddress((void**)&h, g_h);
    cudaGetSymbolAddress((void**)&q, g_q);
    cudaGetSymbolAddress((void**)&k, g_k);
    cudaGetSymbolAddress((void**)&v, g_v);
    cudaGetSymbolAddress((void**)&attn, g_attn);
    cudaGetSymbolAddress((void**)&ff, g_ff);
    cudaGetSymbolAddress((void**)&pq, g_pq);
    cudaGetSymbolAddress((void**)&pk, g_pk);
    cudaGetSymbolAddress((void**)&E1, g_E1);
    cudaGetSymbolAddress((void**)&W1t, g_W1t);
    cudaGetSymbolAddress((void**)&relbias, g_relbias);
    cudaGetSymbolAddress((void**)&wqh, g_wq_hi); cudaGetSymbolAddress((void**)&wql, g_wq_lo);
    cudaGetSymbolAddress((void**)&wkh, g_wk_hi); cudaGetSymbolAddress((void**)&wkl, g_wk_lo);
    cudaGetSymbolAddress((void**)&wvh, g_wv_hi); cudaGetSymbolAddress((void**)&wvl, g_wv_lo);
    cudaGetSymbolAddress((void**)&woh, g_wo_hi); cudaGetSymbolAddress((void**)&wol, g_wo_lo);
    cudaGetSymbolAddress((void**)&f1h, g_f1_hi); cudaGetSymbolAddress((void**)&f1l, g_f1_lo);
    cudaGetSymbolAddress((void**)&f2h, g_f2_hi); cudaGetSymbolAddress((void**)&f2l, g_f2_lo);
    cudaGetSymbolAddress((void**)&pqh, g_pqw_hi); cudaGetSymbolAddress((void**)&pql, g_pqw_lo);
    cudaGetSymbolAddress((void**)&pkh, g_pkw_hi); cudaGetSymbolAddress((void**)&pkl, g_pkw_lo);

    cudaFuncSetAttribute(attn4_kernel, cudaFuncAttributeMaxDynamicSharedMemorySize, ATTN_SMEM);
    cudaFuncSetAttribute(pair_tc2_kernel, cudaFuncAttributeMaxDynamicSharedMemorySize, PAIR_SMEM);

    embed_kernel<<<L, D>>>(seq, tok_emb, x);
    relbias_kernel<<<(H * 1536 + 255) / 256, 256>>>(rp_emb, relbias);
    presplit2_kernel<<<dim3(256, NLAYER), 256>>>(ffn_w1, f1h, f1l, D, DFF);
    presplit2_kernel<<<dim3(64, NLAYER), 256>>>(wq, wqh, wql, D, D);
    presplit2_kernel<<<dim3(64, NLAYER), 256>>>(wk, wkh, wkl, D, D);
    presplit2_kernel<<<dim3(64, NLAYER), 256>>>(wv, wvh, wvl, D, D);
    presplit2_kernel<<<dim3(64, NLAYER), 256>>>(wo, woh, wol, D, D);
    presplit2_kernel<<<dim3(256, NLAYER), 256>>>(ffn_w2, f2h, f2l, DFF, D);
    presplit2_kernel<<<dim3(64, 1), 256>>>(pair_q_w, pqh, pql, D, D);
    presplit2_kernel<<<dim3(64, 1), 256>>>(pair_k_w, pkh, pkl, D, D);
    e1_kernel<<<NB, D>>>(pair_rp, cls_w1, cls_b1, E1);
    w1t_kernel<<<D * D / 256, 256>>>(cls_w1, W1t);

    dim3 gqkv(D / 64, L / 64, 3);
    dim3 g32(D / 64, L / 32);
    dim3 gff1(DFF / 64, L / 64);
    dim3 gpqpk(D / 64, L / 32, 2);

    for (int layer = 0; layer < NLAYER; layer++) {
        ln_kernel<<<L, D>>>(x, ln1_s + layer * D, ln1_b + layer * D, h);
        hgemm_qkv_kernel<<<gqkv, 256>>>(h, layer, q, k, v);
        attn4_kernel<<<dim3(L / QT, H), 256, ATTN_SMEM>>>(q, k, v, relbias, attn);
        hgemm_kernel<4, 32><<<g32, 256>>>(attn, woh + (size_t)layer * D * D,
                                          wol + (size_t)layer * D * D, x,
                                          nullptr, x, L, D, D);
        ln_kernel<<<L, D>>>(x, ln2_s + layer * D, ln2_b + layer * D, h);
        hgemm_kernel<2, 64><<<gff1, 256>>>(h, f1h + (size_t)layer * D * DFF,
                                           f1l + (size_t)layer * D * DFF, ff,
                                           ffn_b1 + layer * DFF, nullptr, L, DFF, D);
        hgemm_kernel<3, 32><<<g32, 256>>>(ff, f2h + (size_t)layer * DFF * D,
                                          f2l + (size_t)layer * DFF * D, x,
                                          ffn_b2 + layer * D, x, L, D, DFF);
    }

    ln_kernel<<<L, D>>>(x, lnf_s, lnf_b, h);
    hgemm_pqpk_kernel<<<gpqpk, 256>>>(h, pair_q_b, pair_k_b, pq, pk);

    pair_tc2_kernel<<<dim3(L / TJ, L / TI), 1024, PAIR_SMEM>>>(
        pq, pk, W1t, E1, cls_w2, cls_b2, out);
}

// round 17
// speedup vs baseline: 1.9938x; 1.0721x over previous
#include <cuda_runtime.h>
#include <cuda_bf16.h>
#include <math.h>

#define L 768
#define D 256
#define H 8
#define DK 32
#define DFF 1024
#define NB 64
#define NLAYER 8

// ---------------- device scratch ----------------
__device__ float g_x[L * D];
__device__ float g_h[L * D];
__device__ float g_q[L * D];
__device__ float g_k[L * D];
__device__ float g_v[L * D];
__device__ float g_attn[L * D];
__device__ float g_ff[L * DFF];
__device__ float g_pq[L * D];
__device__ float g_pk[L * D];
__device__ float g_E1[NB * D];
__device__ unsigned g_W1t[D * D];
__device__ float g_relbias[H * 1536];

__device__ __nv_bfloat16 g_wq_hi[NLAYER * D * D], g_wq_lo[NLAYER * D * D];
__device__ __nv_bfloat16 g_wk_hi[NLAYER * D * D], g_wk_lo[NLAYER * D * D];
__device__ __nv_bfloat16 g_wv_hi[NLAYER * D * D], g_wv_lo[NLAYER * D * D];
__device__ __nv_bfloat16 g_wo_hi[NLAYER * D * D], g_wo_lo[NLAYER * D * D];
__device__ __nv_bfloat16 g_f1_hi[NLAYER * D * DFF], g_f1_lo[NLAYER * D * DFF];
__device__ __nv_bfloat16 g_f2_hi[NLAYER * DFF * D], g_f2_lo[NLAYER * DFF * D];
__device__ __nv_bfloat16 g_pqw_hi[D * D], g_pqw_lo[D * D];
__device__ __nv_bfloat16 g_pkw_hi[D * D], g_pkw_lo[D * D];

// ---------------- helpers ----------------
__device__ __forceinline__ unsigned smem_u32(const void* p) {
    unsigned a;
    asm("{ .reg .u64 t; cvta.to.shared.u64 t, %1; cvt.u32.u64 %0, t; }" : "=r"(a) : "l"(p));
    return a;
}
__device__ __forceinline__ void cp_async16(unsigned saddr, const void* gptr) {
    asm volatile("cp.async.cg.shared.global [%0], [%1], 16;" :: "r"(saddr), "l"(gptr));
}
#define CP_COMMIT() asm volatile("cp.async.commit_group;")
#define CP_WAIT0()  asm volatile("cp.async.wait_group 0;")

__device__ __forceinline__ int bucket_of(int rel) {
    int ret = (rel < 0) ? 32 : 0;
    int arp = abs(rel);
    int val;
    if (arp < 16) {
        val = arp;
    } else {
        float t = logf((float)arp / 16.0f) / 2.7725887f * 16.0f;
        int vil = 16 + (int)t;
        val = vil < 31 ? vil : 31;
    }
    return ret + val;
}

__global__ void relbias_kernel(const float* __restrict__ rp_emb,
                               float* __restrict__ relbias) {
    int idx = blockIdx.x * 256 + threadIdx.x;
    if (idx >= H * 1536) return;
    int h = idx / 1536, r = idx % 1536;
    relbias[idx] = rp_emb[bucket_of(r - 768) * H + h];
}

// ---------------- embedding ----------------
__global__ void embed_kernel(const int* __restrict__ seq,
                             const float* __restrict__ tok_emb,
                             float* __restrict__ x) {
    int l = blockIdx.x;
    int d = threadIdx.x;
    x[l * D + d] = tok_emb[seq[l] * D + d];
}

// ---------------- layernorm ----------------
__global__ void ln_kernel(const float* __restrict__ x,
                          const float* __restrict__ s,
                          const float* __restrict__ b,
                          float* __restrict__ out) {
    int row = blockIdx.x;
    int tid = threadIdx.x;
    float val = x[row * D + tid];
    float s1 = val, s2 = val * val;
#pragma unroll
    for (int o = 16; o > 0; o >>= 1) {
        s1 += __shfl_xor_sync(0xffffffffu, s1, o);
        s2 += __shfl_xor_sync(0xffffffffu, s2, o);
    }
    __shared__ float r1[8], r2[8];
    if ((tid & 31) == 0) { r1[tid >> 5] = s1; r2[tid >> 5] = s2; }
    __syncthreads();
    float t1 = 0.f, t2 = 0.f;
#pragma unroll
    for (int w = 0; w < 8; w++) { t1 += r1[w]; t2 += r2[w]; }
    float m = t1 * (1.0f / D);
    float var = t2 * (1.0f / D) - m * m;
    out[row * D + tid] = (val - m) * rsqrtf(var + 1e-5f) * s[tid] + b[tid];
}

// ---------------- presplit v2 ----------------
__global__ void presplit2_kernel(const float* __restrict__ W,
                                 __nv_bfloat16* __restrict__ hiT,
                                 __nv_bfloat16* __restrict__ loT,
                                 int K, int N) {
    __shared__ float tile[32][33];
    const int tiles_n = N >> 5;
    const int tk = blockIdx.x / tiles_n, tn = blockIdx.x % tiles_n;
    const int l = blockIdx.y;
    const float* Wl = W + (size_t)l * K * N;
    __nv_bfloat16* hl = hiT + (size_t)l * K * N;
    __nv_bfloat16* ll = loT + (size_t)l * K * N;
    const int r = threadIdx.x >> 5, c = threadIdx.x & 31;
#pragma unroll
    for (int p = 0; p < 4; p++)
        tile[r + p * 8][c] = Wl[(size_t)(tk * 32 + r + p * 8) * N + tn * 32 + c];
    __syncthreads();
#pragma unroll
    for (int p = 0; p < 4; p++) {
        int n = tn * 32 + r + p * 8;
        int kk = tk * 32 + c;
        float a = tile[c][r + p * 8];
        __nv_bfloat16 hh = __float2bfloat16(a);
        hl[(size_t)n * K + kk] = hh;
        ll[(size_t)n * K + kk] = __float2bfloat16(a - __bfloat162float(hh));
    }
}

// ---------------- bf16-split HMMA GEMM ----------------
__device__ __forceinline__ float gelu_exact(float x) {
    return 0.5f * x * (1.0f + erff(x * 0.70710678118654752f));
}

__device__ __forceinline__ void mma_bf16(float* c, const unsigned* a, unsigned b0, unsigned b1) {
    asm volatile(
        "mma.sync.aligned.m16n8k16.row.col.f32.bf16.bf16.f32 "
        "{%0,%1,%2,%3}, {%4,%5,%6,%7}, {%8,%9}, {%0,%1,%2,%3};"
        : "+f"(c[0]), "+f"(c[1]), "+f"(c[2]), "+f"(c[3])
        : "r"(a[0]), "r"(a[1]), "r"(a[2]), "r"(a[3]), "r"(b0), "r"(b1));
}

__device__ __forceinline__ unsigned packsplit(float a, float b, unsigned& lo) {
    __nv_bfloat16 ha = __float2bfloat16(a), hb = __float2bfloat16(b);
    __nv_bfloat16 la = __float2bfloat16(a - __bfloat162float(ha));
    __nv_bfloat16 lb = __float2bfloat16(b - __bfloat162float(hb));
    lo = (unsigned)__bfloat16_as_ushort(la) | ((unsigned)__bfloat16_as_ushort(lb) << 16);
    return (unsigned)__bfloat16_as_ushort(ha) | ((unsigned)__bfloat16_as_ushort(hb) << 16);
}

#define HPAD 20

template <int EPI, int BM>
__device__ __forceinline__ void hgemm_body(
    const float* __restrict__ A, const __nv_bfloat16* __restrict__ BhiT,
    const __nv_bfloat16* __restrict__ BloT, float* __restrict__ C,
    const float* __restrict__ bias, const float* __restrict__ res,
    int M, int N, int K, int bx, int by)
{
    constexpr int MI = BM / 32;
    __shared__ unsigned sAhi[2][BM * HPAD], sAlo[2][BM * HPAD];
    __shared__ unsigned sBhi[2][64 * HPAD], sBlo[2][64 * HPAD];
    const int tid = threadIdx.x;
    const int lane = tid & 31, warp = tid >> 5;
    const int gid = lane >> 2, tig = lane & 3;
    const int wm = warp >> 2, wn = warp & 3;
    const int row0 = by * BM, col0 = bx * 64;

    float acc[MI][2][4];
#pragma unroll
    for (int mi = 0; mi < MI; mi++)
#pragma unroll
        for (int ni = 0; ni < 2; ni++)
#pragma unroll
            for (int c = 0; c < 4; c++) acc[mi][ni][c] = 0.f;

    const int arow = tid >> 3;
    const int akq  = (tid & 7) * 4;
    const int bn   = tid >> 2;
    const int bq   = (tid & 3) * 4;

    const float* Ap0 = A + (size_t)(row0 + arow) * K + akq;
    const float* Ap1 = (BM == 64) ? A + (size_t)(row0 + arow + 32) * K + akq : Ap0;
    const __nv_bfloat16* Bph = BhiT + (size_t)(col0 + bn) * K + bq * 2;
    const __nv_bfloat16* Bpl = BloT + (size_t)(col0 + bn) * K + bq * 2;
    unsigned aBhi[2], aBlo[2];
    aBhi[0] = smem_u32(&sBhi[0][bn * HPAD + bq]);
    aBhi[1] = smem_u32(&sBhi[1][bn * HPAD + bq]);
    aBlo[0] = smem_u32(&sBlo[0][bn * HPAD + bq]);
    aBlo[1] = smem_u32(&sBlo[1][bn * HPAD + bq]);

    cp_async16(aBhi[0], Bph);
    cp_async16(aBlo[0], Bpl);
    CP_COMMIT();
    {
        float4 a0 = *(const float4*)Ap0;
        unsigned lo01, lo23;
        unsigned hi01 = packsplit(a0.x, a0.y, lo01);
        unsigned hi23 = packsplit(a0.z, a0.w, lo23);
        uint2 hv; hv.x = hi01; hv.y = hi23;
        uint2 lv; lv.x = lo01; lv.y = lo23;
        *(uint2*)&sAhi[0][arow * HPAD + (akq >> 1)] = hv;
        *(uint2*)&sAlo[0][arow * HPAD + (akq >> 1)] = lv;
        if (BM == 64) {
            float4 a1 = *(const float4*)Ap1;
            hi01 = packsplit(a1.x, a1.y, lo01);
            hi23 = packsplit(a1.z, a1.w, lo23);
            hv.x = hi01; hv.y = hi23;
            lv.x = lo01; lv.y = lo23;
            *(uint2*)&sAhi[0][(arow + 32) * HPAD + (akq >> 1)] = hv;
            *(uint2*)&sAlo[0][(arow + 32) * HPAD + (akq >> 1)] = lv;
        }
    }
    CP_WAIT0();
    __syncthreads();

    const int nch = K / 32;
    for (int ch = 0; ch < nch; ch++) {
        const int cur = ch & 1, nxt = cur ^ 1;
        const bool pf = (ch + 1 < nch);
        float4 a0pre, a1pre;
        if (pf) {
            const int k0n = (ch + 1) * 32;
            cp_async16(aBhi[nxt], Bph + k0n);
            cp_async16(aBlo[nxt], Bpl + k0n);
            CP_COMMIT();
            a0pre = *(const float4*)(Ap0 + k0n);
            if (BM == 64) a1pre = *(const float4*)(Ap1 + k0n);
        }
        const unsigned* bAhi = sAhi[cur];
        const unsigned* bAlo = sAlo[cur];
        const unsigned* bBhi = sBhi[cur];
        const unsigned* bBlo = sBlo[cur];
#pragma unroll
        for (int ks = 0; ks < 2; ks++) {
            const int kb = ks * 8;
            unsigned ahi[MI][4], alo[MI][4];
#pragma unroll
            for (int mi = 0; mi < MI; mi++) {
                int R = wm * (BM / 2) + mi * 16;
                ahi[mi][0] = bAhi[(R + gid) * HPAD + kb + tig];
                ahi[mi][1] = bAhi[(R + gid + 8) * HPAD + kb + tig];
                ahi[mi][2] = bAhi[(R + gid) * HPAD + kb + tig + 4];
                ahi[mi][3] = bAhi[(R + gid + 8) * HPAD + kb + tig + 4];
                alo[mi][0] = bAlo[(R + gid) * HPAD + kb + tig];
                alo[mi][1] = bAlo[(R + gid + 8) * HPAD + kb + tig];
                alo[mi][2] = bAlo[(R + gid) * HPAD + kb + tig + 4];
                alo[mi][3] = bAlo[(R + gid + 8) * HPAD + kb + tig + 4];
            }
#pragma unroll
            for (int ni = 0; ni < 2; ni++) {
                int nc = wn * 16 + ni * 8;
                unsigned bh0 = bBhi[(nc + gid) * HPAD + kb + tig];
                unsigned bh1 = bBhi[(nc + gid) * HPAD + kb + tig + 4];
                unsigned bl0 = bBlo[(nc + gid) * HPAD + kb + tig];
                unsigned bl1 = bBlo[(nc + gid) * HPAD + kb + tig + 4];
#pragma unroll
                for (int mi = 0; mi < MI; mi++) {
                    mma_bf16(acc[mi][ni], ahi[mi], bh0, bh1);
                    mma_bf16(acc[mi][ni], ahi[mi], bl0, bl1);
                    mma_bf16(acc[mi][ni], alo[mi], bh0, bh1);
                }
            }
        }
        if (pf) {
            unsigned lo01, lo23;
            unsigned hi01 = packsplit(a0pre.x, a0pre.y, lo01);
            unsigned hi23 = packsplit(a0pre.z, a0pre.w, lo23);
            uint2 hv; hv.x = hi01; hv.y = hi23;
            uint2 lv; lv.x = lo01; lv.y = lo23;
            *(uint2*)&sAhi[nxt][arow * HPAD + (akq >> 1)] = hv;
            *(uint2*)&sAlo[nxt][arow * HPAD + (akq >> 1)] = lv;
            if (BM == 64) {
                hi01 = packsplit(a1pre.x, a1pre.y, lo01);
                hi23 = packsplit(a1pre.z, a1pre.w, lo23);
                hv.x = hi01; hv.y = hi23;
                lv.x = lo01; lv.y = lo23;
                *(uint2*)&sAhi[nxt][(arow + 32) * HPAD + (akq >> 1)] = hv;
                *(uint2*)&sAlo[nxt][(arow + 32) * HPAD + (akq >> 1)] = lv;
            }
            CP_WAIT0();
        }
        __syncthreads();
    }

#pragma unroll
    for (int mi = 0; mi < MI; mi++) {
#pragma unroll
        for (int ni = 0; ni < 2; ni++) {
            int m0 = row0 + wm * (BM / 2) + mi * 16 + gid;
            int n = col0 + wn * 16 + ni * 8 + tig * 2;
            float v0 = acc[mi][ni][0], v1 = acc[mi][ni][1];
            float v2 = acc[mi][ni][2], v3 = acc[mi][ni][3];
            if (EPI == 1 || EPI == 2 || EPI == 3) {
                float2 bb = *(const float2*)&bias[n];
                v0 += bb.x; v1 += bb.y; v2 += bb.x; v3 += bb.y;
            }
            if (EPI == 2) {
                v0 = gelu_exact(v0); v1 = gelu_exact(v1);
                v2 = gelu_exact(v2); v3 = gelu_exact(v3);
            }
            if (EPI == 3 || EPI == 4) {
                float2 r0 = *(const float2*)&res[(size_t)m0 * N + n];
                float2 r1 = *(const float2*)&res[(size_t)(m0 + 8) * N + n];
                v0 += r0.x; v1 += r0.y; v2 += r1.x; v3 += r1.y;
            }
            float2 o0; o0.x = v0; o0.y = v1;
            float2 o1; o1.x = v2; o1.y = v3;
            *(float2*)&C[(size_t)m0 * N + n] = o0;
            *(float2*)&C[(size_t)(m0 + 8) * N + n] = o1;
        }
    }
}

template <int EPI, int BM>
__global__ void __launch_bounds__(256, 3)
hgemm_kernel(const float* __restrict__ A, const __nv_bfloat16* __restrict__ BhiT,
             const __nv_bfloat16* __restrict__ BloT, float* __restrict__ C,
             const float* __restrict__ bias, const float* __restrict__ res,
             int M, int N, int K) {
    hgemm_body<EPI, BM>(A, BhiT, BloT, C, bias, res, M, N, K, blockIdx.x, blockIdx.y);
}

__global__ void __launch_bounds__(256, 3)
hgemm_qkv_kernel(const float* __restrict__ A, int layer,
                 float* __restrict__ q, float* __restrict__ k, float* __restrict__ v) {
    const size_t off = (size_t)layer * D * D;
    const __nv_bfloat16 *bh, *bl;
    float* C;
    if (blockIdx.z == 0)      { bh = g_wq_hi + off; bl = g_wq_lo + off; C = q; }
    else if (blockIdx.z == 1) { bh = g_wk_hi + off; bl = g_wk_lo + off; C = k; }
    else                      { bh = g_wv_hi + off; bl = g_wv_lo + off; C = v; }
    hgemm_body<0, 64>(A, bh, bl, C, nullptr, nullptr, L, D, D, blockIdx.x, blockIdx.y);
}

__global__ void __launch_bounds__(256, 3)
hgemm_pqpk_kernel(const float* __restrict__ A,
                  const float* __restrict__ bq, const float* __restrict__ bk,
                  float* __restrict__ pq, float* __restrict__ pk) {
    const __nv_bfloat16 *bh, *bl;
    const float* bias;
    float* C;
    if (blockIdx.z == 0) { bh = g_pqw_hi; bl = g_pqw_lo; bias = bq; C = pq; }
    else                 { bh = g_pkw_hi; bl = g_pkw_lo; bias = bk; C = pk; }
    hgemm_body<1, 32>(A, bh, bl, C, bias, nullptr, L, D, D, blockIdx.x, blockIdx.y);
}

// ---------------- attention v4 ----------------
#define QT 16
#define KTPAD 36
#define ATTN_SMEM ((QT * DK + 784 + QT * L + QT + 128 * KTPAD) * 4)
__global__ void __launch_bounds__(256, 3)
attn4_kernel(const float* __restrict__ q, const float* __restrict__ k,
             const float* __restrict__ v, const float* __restrict__ relbias,
             float* __restrict__ out) {
    extern __shared__ unsigned char smraw[];
    float* sq = (float*)smraw;
    float* sbias = sq + QT * DK;
    float* sp = sbias + 784;
    float* sinv = sp + QT * L;
    float* kt = sinv + 16;
    const int i0 = blockIdx.x * QT;
    const int h = blockIdx.y;
    const int tid = threadIdx.x;
    const float invscale = 0.17677669529663687f;

    for (int t = tid; t < QT * DK; t += 256)
        sq[t] = q[(i0 + (t >> 5)) * D + h * DK + (t & 31)];
    for (int t = tid; t < 783; t += 256)
        sbias[t] = relbias[h * 1536 + i0 + 1 + t];

    const int srow = tid >> 3;
    const int scol = (tid & 7) * 4;
    const int jl = tid & 127;
    const int qb = (tid >> 7) * 8;
    __syncthreads();

    for (int jt = 0; jt < 6; jt++) {
        const int j0t = jt * 128;
        if (jt) __syncthreads();
#pragma unroll
        for (int p = 0; p < 4; p++) {
            int row = srow + p * 32;
            float4 kv = *(const float4*)(k + (size_t)(j0t + row) * D + h * DK + scol);
            *(float4*)(kt + row * KTPAD + scol) = kv;
        }
        __syncthreads();
        float4 kv[8];
#pragma unroll
        for (int t = 0; t < 8; t++) kv[t] = *(const float4*)(kt + jl * KTPAD + t * 4);
        float dot[8];
#pragma unroll
        for (int u = 0; u < 8; u++) dot[u] = 0.f;
#pragma unroll
        for (int t = 0; t < 8; t++) {
#pragma unroll
            for (int u = 0; u < 8; u++) {
                float4 qv = *(const float4*)(sq + (qb + u) * DK + t * 4);
                dot[u] += qv.x * kv[t].x + qv.y * kv[t].y + qv.z * kv[t].z + qv.w * kv[t].w;
            }
        }
        const int j = j0t + jl;
#pragma unroll
        for (int u = 0; u < 8; u++)
            sp[(qb + u) * L + j] = dot[u] * invscale + sbias[(qb + u) - j + 767];
    }
    __syncthreads();

    const int warp = tid >> 5, lane = tid & 31;
#pragma unroll
    for (int qq = 0; qq < 2; qq++) {
        int qi = warp * 2 + qq;
        float m = -1e30f;
        for (int j = lane; j < L; j += 32) m = fmaxf(m, sp[qi * L + j]);
#pragma unroll
        for (int o = 16; o > 0; o >>= 1) m = fmaxf(m, __shfl_xor_sync(0xffffffffu, m, o));
        float s = 0.f;
        for (int j = lane; j < L; j += 32) {
            float e = expf(sp[qi * L + j] - m);
            sp[qi * L + j] = e;
            s += e;
        }
#pragma unroll
        for (int o = 16; o > 0; o >>= 1) s += __shfl_xor_sync(0xffffffffu, s, o);
        if (lane == 0) sinv[qi] = 1.0f / s;
    }

    const int qiA = warp * 2, qiB = qiA + 1;
    const int jsub = lane >> 3, dq = lane & 7;
    float4 a0 = make_float4(0, 0, 0, 0), a1 = make_float4(0, 0, 0, 0);
    const float* spA = sp + qiA * L;
    const float* spB = sp + qiB * L;
    for (int jt = 0; jt < 6; jt++) {
        const int j0t = jt * 128;
        __syncthreads();
#pragma unroll
        for (int p = 0; p < 4; p++) {
            int row = srow + p * 32;
            float4 vv = *(const float4*)(v + (size_t)(j0t + row) * D + h * DK + scol);
            *(float4*)(kt + row * KTPAD + scol) = vv;
        }
        __syncthreads();
#pragma unroll 4
        for (int jj = 0; jj < 128; jj += 4) {
            int r = jj + jsub;
            float4 vv = *(const float4*)(kt + r * KTPAD + dq * 4);
            float sA = spA[j0t + r], sB = spB[j0t + r];
            a0.x += sA * vv.x; a0.y += sA * vv.y; a0.z += sA * vv.z; a0.w += sA * vv.w;
            a1.x += sB * vv.x; a1.y += sB * vv.y; a1.z += sB * vv.z; a1.w += sB * vv.w;
        }
    }
#pragma unroll
    for (int o = 8; o <= 16; o <<= 1) {
        a0.x += __shfl_xor_sync(0xffffffffu, a0.x, o);
        a0.y += __shfl_xor_sync(0xffffffffu, a0.y, o);
        a0.z += __shfl_xor_sync(0xffffffffu, a0.z, o);
        a0.w += __shfl_xor_sync(0xffffffffu, a0.w, o);
        a1.x += __shfl_xor_sync(0xffffffffu, a1.x, o);
        a1.y += __shfl_xor_sync(0xffffffffu, a1.y, o);
        a1.z += __shfl_xor_sync(0xffffffffu, a1.z, o);
        a1.w += __shfl_xor_sync(0xffffffffu, a1.w, o);
    }
    if (jsub == 0) {
        float iA = sinv[qiA], iB = sinv[qiB];
        float4 oA = make_float4(a0.x * iA, a0.y * iA, a0.z * iA, a0.w * iA);
        float4 oB = make_float4(a1.x * iB, a1.y * iB, a1.z * iB, a1.w * iB);
        *(float4*)(out + (size_t)(i0 + qiA) * D + h * DK + dq * 4) = oA;
        *(float4*)(out + (size_t)(i0 + qiB) * D + h * DK + dq * 4) = oB;
    }
}

// ---------------- E1 ----------------
__global__ void e1_kernel(const float* __restrict__ rp, const float* __restrict__ W1,
                          const float* __restrict__ b1, float* __restrict__ E1) {
    int b = blockIdx.x;
    int d = threadIdx.x;
    float s = b1[d];
    for (int c = 0; c < D; c++) s += rp[b * D + c] * W1[c * D + d];
    E1[b * D + d] = s;
}

// ---------------- tf32 helpers (pair head) ----------------
__device__ __forceinline__ unsigned f2tf32(float x) {
    unsigned r;
    asm("cvt.rna.tf32.f32 %0, %1;" : "=r"(r) : "f"(x));
    return r;
}

__device__ __forceinline__ void mma_tf32(float* c, const unsigned* a, unsigned b0, unsigned b1) {
    asm volatile(
        "mma.sync.aligned.m16n8k8.row.col.f32.tf32.tf32.f32 "
        "{%0,%1,%2,%3}, {%4,%5,%6,%7}, {%8,%9}, {%0,%1,%2,%3};"
        : "+f"(c[0]), "+f"(c[1]), "+f"(c[2]), "+f"(c[3])
        : "r"(a[0]), "r"(a[1]), "r"(a[2]), "r"(a[3]), "r"(b0), "r"(b1));
}

__global__ void w1t_kernel(const float* __restrict__ W1, unsigned* __restrict__ W1t) {
    int t = blockIdx.x * 256 + threadIdx.x;
    W1t[t] = f2tf32(W1[t]);
}

// ---------------- pair head: tf32 HMMA, 512 threads, cp.async pipeline -----
#define TI 4
#define TJ 32
#define PAD_A 36
#define PAD_B 264
#define PAD_E 260
#define AS_STRIDE (128 * PAD_A)
#define WS_STRIDE (32 * PAD_B)
#define PAIR_SMEM ((1024 + 512 + 1024 + NB * PAD_E + 2 * AS_STRIDE + 2 * WS_STRIDE) * 4)

__global__ void __launch_bounds__(512, 1)
pair_tc2_kernel(const float* __restrict__ pq, const float* __restrict__ pk,
                const unsigned* __restrict__ W1t, const float* __restrict__ E1,
                const float* __restrict__ W2, const float* __restrict__ b2,
                float* __restrict__ out) {
    extern __shared__ unsigned char smraw[];
    float*    qs  = (float*)smraw;                 // [4][256]
    float*    w2s = qs + 1024;                     // [512]
    float*    red = w2s + 512;                     // [4][128][2]
    float*    E1s = red + 1024;                    // [64][PAD_E]
    unsigned* As  = (unsigned*)(E1s + NB * PAD_E); // 2 x [128][PAD_A]
    unsigned* Ws  = As + 2 * AS_STRIDE;            // 2 x [32][PAD_B]

    const int i0 = blockIdx.y * TI;
    const int j0 = blockIdx.x * TJ;
    const int tid = threadIdx.x;
    const int lane = tid & 31, warp = tid >> 5;    // 16 warps
    const int gid = lane >> 2, tig = lane & 3;
    const int wm = warp >> 2;   // 0..3 -> pairs wm*32
    const int wn = warp & 3;    // 0..3 -> d cols wn*64

    if (tid < 256) ((float4*)qs)[tid] = ((const float4*)(pq + (size_t)i0 * D))[tid];
    w2s[tid] = W2[tid];
    // E1 -> smem: 4096 float4 over 512 threads
#pragma unroll
    for (int t = 0; t < 8; t++) {
        int idx = tid + t * 512;
        int b = idx >> 6, d4 = (idx & 63) << 2;
        *(float4*)&E1s[b * PAD_E + d4] = *(const float4*)&E1[b * D + d4];
    }

    float acc[2][8][4] = {};

    // A fill: 128 pairs x 32 c = 1024 float4 over 512 threads -> 2 each
    const int pfill = tid >> 2;              // 0..127
    const int ccb = (tid & 3) * 8;           // 0,8,16,24
    const int ilf = pfill >> 5, jlf = pfill & 31;
    const float* pkrow = pk + (size_t)(j0 + jlf) * D;
    const float* qsrow = qs + ilf * D;
    // Ws fill: 2048 uint4 over 512 -> 4 cp.async each
    const int wr0 = tid >> 6;                // rows wr0 + t*8 (0..31)
    const int wc0 = (tid & 63) << 2;

    unsigned aWs[2][4];
#pragma unroll
    for (int t = 0; t < 4; t++) {
        int row = wr0 + t * 8;
        aWs[0][t] = smem_u32(&Ws[0 * WS_STRIDE + row * PAD_B + wc0]);
        aWs[1][t] = smem_u32(&Ws[1 * WS_STRIDE + row * PAD_B + wc0]);
    }
    const unsigned* Wg = W1t + (size_t)wr0 * D + wc0;   // W1t[c][d]: row stride D

    // ---- initial fill of buffer 0 (k0 = 0) ----
#pragma unroll
    for (int t = 0; t < 4; t++)
        cp_async16(aWs[0][t], Wg + (size_t)(t * 8) * D);
    CP_COMMIT();
    __syncthreads();   // qs visible before A-tile build
    {
        const float4* kr = (const float4*)(pkrow + ccb);
        const float4* qr = (const float4*)(qsrow + ccb);
        uint4* da = (uint4*)(As + pfill * PAD_A + ccb);
#pragma unroll
        for (int t = 0; t < 2; t++) {
            float4 kv = kr[t], qv = qr[t];
            uint4 o;
            o.x = f2tf32(kv.x * qv.x);
            o.y = f2tf32(kv.y * qv.y);
            o.z = f2tf32(kv.z * qv.z);
            o.w = f2tf32(kv.w * qv.w);
            da[t] = o;
        }
    }
    CP_WAIT0();
    __syncthreads();

    for (int ch = 0; ch < 8; ch++) {
        const int cur = ch & 1, nxt = cur ^ 1;
        const int k0n = (ch + 1) * 32;
        const bool pf = (ch < 7);
        float4 krpre[2];
        if (pf) {
            // k advances in ROWS of W1t (stride D): rows k0n + wr0 + t*8
#pragma unroll
            for (int t = 0; t < 4; t++)
                cp_async16(aWs[nxt][t], Wg + (size_t)(k0n + t * 8) * D);
            CP_COMMIT();
            const float4* kr = (const float4*)(pkrow + k0n + ccb);
            krpre[0] = kr[0];
            krpre[1] = kr[1];
        }
        // ---- MMA on buffer cur ----
        const unsigned* Ab = As + cur * AS_STRIDE;
        const unsigned* Wb = Ws + cur * WS_STRIDE;
#pragma unroll
        for (int kf = 0; kf < 4; kf++) {
            unsigned a[2][4];
#pragma unroll
            for (int mi = 0; mi < 2; mi++) {
                int R = wm * 32 + mi * 16;
                a[mi][0] = Ab[(R + gid) * PAD_A + kf * 8 + tig];
                a[mi][1] = Ab[(R + gid + 8) * PAD_A + kf * 8 + tig];
                a[mi][2] = Ab[(R + gid) * PAD_A + kf * 8 + tig + 4];
                a[mi][3] = Ab[(R + gid + 8) * PAD_A + kf * 8 + tig + 4];
            }
#pragma unroll
            for (int ni = 0; ni < 8; ni++) {
                unsigned b0 = Wb[(kf * 8 + tig) * PAD_B + wn * 64 + ni * 8 + gid];
                unsigned b1 = Wb[(kf * 8 + tig + 4) * PAD_B + wn * 64 + ni * 8 + gid];
                mma_tf32(acc[0][ni], a[0], b0, b1);
                mma_tf32(acc[1][ni], a[1], b0, b1);
            }
        }
        if (pf) {
            const float4* qr = (const float4*)(qsrow + k0n + ccb);
            uint4* da = (uint4*)(As + nxt * AS_STRIDE + pfill * PAD_A + ccb);
#pragma unroll
            for (int t = 0; t < 2; t++) {
                float4 kv = krpre[t], qv = qr[t];
                uint4 o;
                o.x = f2tf32(kv.x * qv.x);
                o.y = f2tf32(kv.y * qv.y);
                o.z = f2tf32(kv.z * qv.z);
                o.w = f2tf32(kv.w * qv.w);
                da[t] = o;
            }
            CP_WAIT0();
        }
        __syncthreads();
    }

    // epilogue: +E1s[bucket(rel)], relu, @W2 (float2), deterministic reduce
    const float2* w2f = (const float2*)w2s;
#pragma unroll
    for (int mi = 0; mi < 2; mi++) {
#pragma unroll
        for (int half = 0; half < 2; half++) {
            int pl = wm * 32 + mi * 16 + gid + half * 8;   // 0..127
            int il = pl >> 5, jl = pl & 31;
            const float* e1row = E1s + (size_t)bucket_of((i0 + il) - (j0 + jl)) * PAD_E;
            float p0 = 0.f, p1 = 0.f;
#pragma unroll
            for (int ni = 0; ni < 8; ni++) {
#pragma unroll
                for (int col = 0; col < 2; col++) {
                    int d = wn * 64 + ni * 8 + tig * 2 + col;
                    float hv = fmaxf(acc[mi][ni][half * 2 + col] + e1row[d], 0.f);
                    float2 w2v = w2f[d];
                    p0 += hv * w2v.x;
                    p1 += hv * w2v.y;
                }
            }
            p0 += __shfl_xor_sync(0xffffffffu, p0, 1);
            p0 += __shfl_xor_sync(0xffffffffu, p0, 2);
            p1 += __shfl_xor_sync(0xffffffffu, p1, 1);
            p1 += __shfl_xor_sync(0xffffffffu, p1, 2);
            if (tig == 0) {
                red[(wn * 128 + pl) * 2]     = p0;
                red[(wn * 128 + pl) * 2 + 1] = p1;
            }
        }
    }
    __syncthreads();
    if (tid < 256) {
        int pl = tid >> 1, comp = tid & 1;
        int il = pl >> 5, jl = pl & 31;
        float s = red[(0 * 128 + pl) * 2 + comp] + red[(1 * 128 + pl) * 2 + comp]
                + red[(2 * 128 + pl) * 2 + comp] + red[(3 * 128 + pl) * 2 + comp];
        out[((long)(i0 + il) * L + (j0 + jl)) * 2 + comp] = s + b2[comp];
    }
}

// ---------------- host launch ----------------
extern "C" void kernel_launch(void* const* d_in, const int* in_sizes, int n_in,
                              void* d_out, int out_size) {
    const int*   seq      = (const int*)d_in[0];
    const float* tok_emb  = (const float*)d_in[1];
    const float* rp_emb   = (const float*)d_in[2];
    const float* wq       = (const float*)d_in[3];
    const float* wk       = (const float*)d_in[4];
    const float* wv       = (const float*)d_in[5];
    const float* wo       = (const float*)d_in[6];
    const float* ln1_s    = (const float*)d_in[7];
    const float* ln1_b    = (const float*)d_in[8];
    const float* ln2_s    = (const float*)d_in[9];
    const float* ln2_b    = (const float*)d_in[10];
    const float* ffn_w1   = (const float*)d_in[11];
    const float* ffn_b1   = (const float*)d_in[12];
    const float* ffn_w2   = (const float*)d_in[13];
    const float* ffn_b2   = (const float*)d_in[14];
    const float* lnf_s    = (const float*)d_in[15];
    const float* lnf_b    = (const float*)d_in[16];
    const float* pair_q_w = (const float*)d_in[17];
    const float* pair_q_b = (const float*)d_in[18];
    const float* pair_k_w = (const float*)d_in[19];
    const float* pair_k_b = (const float*)d_in[20];
    const float* pair_rp  = (const float*)d_in[21];
    const float* cls_w1   = (const float*)d_in[22];
    const float* cls_b1   = (const float*)d_in[23];
    const float* cls_w2   = (const float*)d_in[24];
    const float* cls_b2   = (const float*)d_in[25];
    float* out = (float*)d_out;

    float *x, *h, *q, *k, *v, *attn, *ff, *pq, *pk, *E1, *relbias;
    unsigned* W1t;
    __nv_bfloat16 *wqh, *wql, *wkh, *wkl, *wvh, *wvl, *woh, *wol;
    __nv_bfloat16 *f1h, *f1l, *f2h, *f2l, *pqh, *pql, *pkh, *pkl;
    cudaGetSymbolAddress((void**)&x, g_x);
    cudaGetSymbolAddress((void**)&h, g_h);
    cudaGetSymbolAddress((void**)&q, g_q);
    cudaGetSymbolAddress((void**)&k, g_k);
    cudaGetSymbolAddress((void**)&v, g_v);
    cudaGetSymbolAddress((void**)&attn, g_attn);
    cudaGetSymbolAddress((void**)&ff, g_ff);
    cudaGetSymbolAddress((void**)&pq, g_pq);
    cudaGetSymbolAddress((void**)&pk, g_pk);
    cudaGetSymbolAddress((void**)&E1, g_E1);
    cudaGetSymbolAddress((void**)&W1t, g_W1t);
    cudaGetSymbolAddress((void**)&relbias, g_relbias);
    cudaGetSymbolAddress((void**)&wqh, g_wq_hi); cudaGetSymbolAddress((void**)&wql, g_wq_lo);
    cudaGetSymbolAddress((void**)&wkh, g_wk_hi); cudaGetSymbolAddress((void**)&wkl, g_wk_lo);
    cudaGetSymbolAddress((void**)&wvh, g_wv_hi); cudaGetSymbolAddress((void**)&wvl, g_wv_lo);
    cudaGetSymbolAddress((void**)&woh, g_wo_hi); cudaGetSymbolAddress((void**)&wol, g_wo_lo);
    cudaGetSymbolAddress((void**)&f1h, g_f1_hi); cudaGetSymbolAddress((void**)&f1l, g_f1_lo);
    cudaGetSymbolAddress((void**)&f2h, g_f2_hi); cudaGetSymbolAddress((void**)&f2l, g_f2_lo);
    cudaGetSymbolAddress((void**)&pqh, g_pqw_hi); cudaGetSymbolAddress((void**)&pql, g_pqw_lo);
    cudaGetSymbolAddress((void**)&pkh, g_pkw_hi); cudaGetSymbolAddress((void**)&pkl, g_pkw_lo);

    cudaFuncSetAttribute(attn4_kernel, cudaFuncAttributeMaxDynamicSharedMemorySize, ATTN_SMEM);
    cudaFuncSetAttribute(pair_tc2_kernel, cudaFuncAttributeMaxDynamicSharedMemorySize, PAIR_SMEM);

    embed_kernel<<<L, D>>>(seq, tok_emb, x);
    relbias_kernel<<<(H * 1536 + 255) / 256, 256>>>(rp_emb, relbias);
    presplit2_kernel<<<dim3(256, NLAYER), 256>>>(ffn_w1, f1h, f1l, D, DFF);
    presplit2_kernel<<<dim3(64, NLAYER), 256>>>(wq, wqh, wql, D, D);
    presplit2_kernel<<<dim3(64, NLAYER), 256>>>(wk, wkh, wkl, D, D);
    presplit2_kernel<<<dim3(64, NLAYER), 256>>>(wv, wvh, wvl, D, D);
    presplit2_kernel<<<dim3(64, NLAYER), 256>>>(wo, woh, wol, D, D);
    presplit2_kernel<<<dim3(256, NLAYER), 256>>>(ffn_w2, f2h, f2l, DFF, D);
    presplit2_kernel<<<dim3(64, 1), 256>>>(pair_q_w, pqh, pql, D, D);
    presplit2_kernel<<<dim3(64, 1), 256>>>(pair_k_w, pkh, pkl, D, D);
    e1_kernel<<<NB, D>>>(pair_rp, cls_w1, cls_b1, E1);
    w1t_kernel<<<D * D / 256, 256>>>(cls_w1, W1t);

    dim3 gqkv(D / 64, L / 64, 3);
    dim3 g32(D / 64, L / 32);
    dim3 gff1(DFF / 64, L / 64);
    dim3 gpqpk(D / 64, L / 32, 2);

    for (int layer = 0; layer < NLAYER; layer++) {
        ln_kernel<<<L, D>>>(x, ln1_s + layer * D, ln1_b + layer * D, h);
        hgemm_qkv_kernel<<<gqkv, 256>>>(h, layer, q, k, v);
        attn4_kernel<<<dim3(L / QT, H), 256, ATTN_SMEM>>>(q, k, v, relbias, attn);
        hgemm_kernel<4, 32><<<g32, 256>>>(attn, woh + (size_t)layer * D * D,
                                          wol + (size_t)layer * D * D, x,
                                          nullptr, x, L, D, D);
        ln_kernel<<<L, D>>>(x, ln2_s + layer * D, ln2_b + layer * D, h);
        hgemm_kernel<2, 64><<<gff1, 256>>>(h, f1h + (size_t)layer * D * DFF,
                                           f1l + (size_t)layer * D * DFF, ff,
                                           ffn_b1 + layer * DFF, nullptr, L, DFF, D);
        hgemm_kernel<3, 32><<<g32, 256>>>(ff, f2h + (size_t)layer * DFF * D,
                                          f2l + (size_t)layer * DFF * D, x,
                                          ffn_b2 + layer * D, x, L, D, DFF);
    }

    ln_kernel<<<L, D>>>(x, lnf_s, lnf_b, h);
    hgemm_pqpk_kernel<<<gpqpk, 256>>>(h, pair_q_b, pair_k_b, pq, pk);

    pair_tc2_kernel<<<dim3(L / TJ, L / TI), 512, PAIR_SMEM>>>(
        pq, pk, W1t, E1, cls_w2, cls_b2, out);
}